// round 6
// baseline (speedup 1.0000x reference)
#include <cuda_runtime.h>
#include <cuda_bf16.h>
#include <math.h>
#include <stdint.h>

#define BATCH 2
#define NSEQ  2048
#define DMODEL 2048
#define HEADS 16
#define DHEAD 128
#define ROWS (BATCH*NSEQ)   // 4096

// ---------------------------------------------------------------------------
// scratch (device globals: no allocation allowed)
// ---------------------------------------------------------------------------
__device__ __nv_bfloat16 g_xhi[ROWS*DMODEL];
__device__ __nv_bfloat16 g_xlo[ROWS*DMODEL];
__device__ __nv_bfloat16 g_ahi[ROWS*DMODEL];
__device__ __nv_bfloat16 g_alo[ROWS*DMODEL];
__device__ __nv_bfloat16 g_qh[ROWS*DMODEL];
__device__ __nv_bfloat16 g_ql[ROWS*DMODEL];
__device__ __nv_bfloat16 g_kh[ROWS*DMODEL];
__device__ __nv_bfloat16 g_kl[ROWS*DMODEL];
__device__ __nv_bfloat16 g_vh[ROWS*DMODEL];
__device__ __nv_bfloat16 g_vl[ROWS*DMODEL];
__device__ __nv_bfloat16 g_wq_hi[DMODEL*DMODEL];
__device__ __nv_bfloat16 g_wq_lo[DMODEL*DMODEL];
__device__ __nv_bfloat16 g_wk_hi[DMODEL*DMODEL];
__device__ __nv_bfloat16 g_wk_lo[DMODEL*DMODEL];
__device__ __nv_bfloat16 g_wv_hi[DMODEL*DMODEL];
__device__ __nv_bfloat16 g_wv_lo[DMODEL*DMODEL];
__device__ __nv_bfloat16 g_wo_hi[DMODEL*DMODEL];
__device__ __nv_bfloat16 g_wo_lo[DMODEL*DMODEL];

// ---------------------------------------------------------------------------
// helpers
// ---------------------------------------------------------------------------
__device__ __forceinline__ uint32_t smem_u32(const void* p) {
    uint32_t a;
    asm("{ .reg .u64 t; cvta.to.shared.u64 t, %1; cvt.u32.u64 %0, t; }" : "=r"(a) : "l"(p));
    return a;
}

__device__ __forceinline__ void cp16(uint32_t dst, const void* src) {
    asm volatile("cp.async.cg.shared.global [%0], [%1], 16;" :: "r"(dst), "l"(src));
}
#define CP_COMMIT() asm volatile("cp.async.commit_group;" ::: "memory")
#define CP_WAIT(n)  asm volatile("cp.async.wait_group %0;" :: "n"(n) : "memory")

__device__ __forceinline__ void ldmx4(uint32_t addr, uint32_t& r0, uint32_t& r1,
                                      uint32_t& r2, uint32_t& r3) {
    asm volatile("ldmatrix.sync.aligned.m8n8.x4.shared.b16 {%0,%1,%2,%3}, [%4];"
                 : "=r"(r0), "=r"(r1), "=r"(r2), "=r"(r3) : "r"(addr));
}
__device__ __forceinline__ void ldmx4t(uint32_t addr, uint32_t& r0, uint32_t& r1,
                                       uint32_t& r2, uint32_t& r3) {
    asm volatile("ldmatrix.sync.aligned.m8n8.x4.trans.shared.b16 {%0,%1,%2,%3}, [%4];"
                 : "=r"(r0), "=r"(r1), "=r"(r2), "=r"(r3) : "r"(addr));
}

__device__ __forceinline__ void mma16816(float& c0, float& c1, float& c2, float& c3,
                                         uint32_t a0, uint32_t a1, uint32_t a2, uint32_t a3,
                                         uint32_t b0, uint32_t b1) {
    asm volatile(
        "mma.sync.aligned.m16n8k16.row.col.f32.bf16.bf16.f32 "
        "{%0,%1,%2,%3}, {%4,%5,%6,%7}, {%8,%9}, {%0,%1,%2,%3};"
        : "+f"(c0), "+f"(c1), "+f"(c2), "+f"(c3)
        : "r"(a0), "r"(a1), "r"(a2), "r"(a3), "r"(b0), "r"(b1));
}

__device__ __forceinline__ uint32_t packbf(float a, float b) {
    __nv_bfloat162 t = __floats2bfloat162_rn(a, b);
    return *(uint32_t*)&t;
}

// ---------------------------------------------------------------------------
// split: fp32 -> (hi, lo) bf16 pair
// ---------------------------------------------------------------------------
__global__ __launch_bounds__(256)
void split_kernel(const float4* __restrict__ in, __nv_bfloat16* __restrict__ hi,
                  __nv_bfloat16* __restrict__ lo, int n4)
{
    int i = blockIdx.x * 256 + threadIdx.x;
    if (i >= n4) return;
    float4 v = in[i];
    __nv_bfloat16 h0 = __float2bfloat16(v.x);
    __nv_bfloat16 h1 = __float2bfloat16(v.y);
    __nv_bfloat16 h2 = __float2bfloat16(v.z);
    __nv_bfloat16 h3 = __float2bfloat16(v.w);
    __nv_bfloat162* hp = (__nv_bfloat162*)(hi + 4 * (size_t)i);
    hp[0] = __nv_bfloat162(h0, h1);
    hp[1] = __nv_bfloat162(h2, h3);
    __nv_bfloat162* lp = (__nv_bfloat162*)(lo + 4 * (size_t)i);
    lp[0] = __nv_bfloat162(__float2bfloat16(v.x - __bfloat162float(h0)),
                           __float2bfloat16(v.y - __bfloat162float(h1)));
    lp[1] = __nv_bfloat162(__float2bfloat16(v.z - __bfloat162float(h2)),
                           __float2bfloat16(v.w - __bfloat162float(h3)));
}

// ---------------------------------------------------------------------------
// transpose + split: W[K][N] fp32 -> Wt[N][K] bf16 (hi, lo)
// ---------------------------------------------------------------------------
__global__ __launch_bounds__(256)
void transpose_split(const float* __restrict__ W, __nv_bfloat16* __restrict__ th,
                     __nv_bfloat16* __restrict__ tl)
{
    __shared__ float t[32][33];
    int n0 = blockIdx.x * 32, k0 = blockIdx.y * 32;
    int tx = threadIdx.x & 31, ty = threadIdx.x >> 5;   // 32 x 8
#pragma unroll
    for (int i = 0; i < 32; i += 8)
        t[ty + i][tx] = W[(size_t)(k0 + ty + i) * DMODEL + n0 + tx];
    __syncthreads();
#pragma unroll
    for (int i = 0; i < 32; i += 8) {
        float v = t[tx][ty + i];
        __nv_bfloat16 h = __float2bfloat16(v);
        size_t o = (size_t)(n0 + ty + i) * DMODEL + k0 + tx;
        th[o] = h;
        tl[o] = __float2bfloat16(v - __bfloat162float(h));
    }
}

// ---------------------------------------------------------------------------
// GEMM tiles / pipeline config
// ---------------------------------------------------------------------------
#define GK DMODEL
#define TM 128
#define TN 128
#define KC 32
#define RSTR 40
#define TILE_B (128u * RSTR * 2u)
#define STAGE_B (4u * TILE_B)
#define GEMM_SMEM (2u * STAGE_B)     // 81920 B (also holds 128x132 fp32 epilogue tile)

// ---------------------------------------------------------------------------
// GEMM mainloop body (shared by both GEMM kernels), single sync per chunk:
//   wait(copy c) -> sync -> issue copy(c+1) -> compute(c)
// ---------------------------------------------------------------------------
#define GEMM_MAINLOOP(ACC)                                                              \
    const int NCH = GK / KC;                                                            \
    copy_chunk(0, 0);                                                                   \
    const uint32_t lrow = (uint32_t)(lane & 15);                                        \
    const uint32_t lcol = (uint32_t)((lane >> 4) & 1) * 8u;                             \
    for (int c = 0; c < NCH; c++) {                                                     \
        int stg = c & 1;                                                                \
        CP_WAIT(0);                                                                     \
        __syncthreads();                                                                \
        if (c + 1 < NCH) copy_chunk(c + 1, stg ^ 1);                                    \
        uint32_t base = sb + (uint32_t)stg * STAGE_B;                                   \
        uint32_t ah_b = base;                                                           \
        uint32_t al_b = base + TILE_B;                                                  \
        uint32_t bh_b = base + 2u * TILE_B;                                             \
        uint32_t bl_b = base + 3u * TILE_B;                                             \
        _Pragma("unroll")                                                               \
        for (int kk = 0; kk < 2; kk++) {                                                \
            uint32_t koff = (uint32_t)(kk * 16) * 2u + lcol * 2u;                       \
            uint32_t Ah[4][4], Al[4][4];                                                \
            _Pragma("unroll")                                                           \
            for (int mi = 0; mi < 4; mi++) {                                            \
                uint32_t roff = ((uint32_t)(wm * 64 + mi * 16) + lrow) * (RSTR * 2u) + koff; \
                ldmx4(ah_b + roff, Ah[mi][0], Ah[mi][1], Ah[mi][2], Ah[mi][3]);         \
                ldmx4(al_b + roff, Al[mi][0], Al[mi][1], Al[mi][2], Al[mi][3]);         \
            }                                                                           \
            uint32_t Bh[4][2], Bl[4][2];                                                \
            _Pragma("unroll")                                                           \
            for (int np = 0; np < 2; np++) {                                            \
                uint32_t roff = ((uint32_t)(wn * 32 + np * 16) + lrow) * (RSTR * 2u) + koff; \
                uint32_t r0, r1, r2, r3;                                                \
                ldmx4(bh_b + roff, r0, r1, r2, r3);                                     \
                Bh[np * 2][0] = r0; Bh[np * 2 + 1][0] = r1;                             \
                Bh[np * 2][1] = r2; Bh[np * 2 + 1][1] = r3;                             \
                ldmx4(bl_b + roff, r0, r1, r2, r3);                                     \
                Bl[np * 2][0] = r0; Bl[np * 2 + 1][0] = r1;                             \
                Bl[np * 2][1] = r2; Bl[np * 2 + 1][1] = r3;                             \
            }                                                                           \
            _Pragma("unroll")                                                           \
            for (int mi = 0; mi < 4; mi++)                                              \
                _Pragma("unroll")                                                       \
                for (int ni = 0; ni < 4; ni++) {                                        \
                    mma16816(ACC[mi][ni][0], ACC[mi][ni][1], ACC[mi][ni][2], ACC[mi][ni][3], \
                             Ah[mi][0], Ah[mi][1], Ah[mi][2], Ah[mi][3],                \
                             Bh[ni][0], Bh[ni][1]);                                     \
                    mma16816(ACC[mi][ni][0], ACC[mi][ni][1], ACC[mi][ni][2], ACC[mi][ni][3], \
                             Ah[mi][0], Ah[mi][1], Ah[mi][2], Ah[mi][3],                \
                             Bl[ni][0], Bl[ni][1]);                                     \
                    mma16816(ACC[mi][ni][0], ACC[mi][ni][1], ACC[mi][ni][2], ACC[mi][ni][3], \
                             Al[mi][0], Al[mi][1], Al[mi][2], Al[mi][3],                \
                             Bh[ni][0], Bh[ni][1]);                                     \
                }                                                                       \
        }                                                                               \
    }

// ---------------------------------------------------------------------------
// Fused QKV GEMM + rotary + bf16 split epilogue. grid (48, 32).
// ---------------------------------------------------------------------------
__global__ __launch_bounds__(256)
void gemm_qkv(const __nv_bfloat16* __restrict__ xhi, const __nv_bfloat16* __restrict__ xlo,
              const __nv_bfloat16* __restrict__ wqh, const __nv_bfloat16* __restrict__ wql,
              const __nv_bfloat16* __restrict__ wkh, const __nv_bfloat16* __restrict__ wkl,
              const __nv_bfloat16* __restrict__ wvh, const __nv_bfloat16* __restrict__ wvl,
              const float* __restrict__ bq, const float* __restrict__ bk,
              const float* __restrict__ bv,
              __nv_bfloat16* __restrict__ qh, __nv_bfloat16* __restrict__ ql,
              __nv_bfloat16* __restrict__ kh, __nv_bfloat16* __restrict__ kl,
              __nv_bfloat16* __restrict__ vh, __nv_bfloat16* __restrict__ vl)
{
    extern __shared__ __align__(128) char smem[];
    uint32_t sb = smem_u32(smem);
    const int tid  = threadIdx.x;
    const int wid  = tid >> 5;
    const int lane = tid & 31;
    const int brow = blockIdx.y * TM;
    const int mtx  = blockIdx.x >> 4;            // 0=q, 1=k, 2=v
    const int bcol = (blockIdx.x & 15) * TN;

    const __nv_bfloat16* Bhi = (mtx == 0) ? wqh : (mtx == 1) ? wkh : wvh;
    const __nv_bfloat16* Blo = (mtx == 0) ? wql : (mtx == 1) ? wkl : wvl;
    const float* bias        = (mtx == 0) ? bq  : (mtx == 1) ? bk  : bv;
    __nv_bfloat16* Oh        = (mtx == 0) ? qh  : (mtx == 1) ? kh  : vh;
    __nv_bfloat16* Ol        = (mtx == 0) ? ql  : (mtx == 1) ? kl  : vl;

    const int wm = wid & 1;
    const int wn = wid >> 1;

    float acc[4][4][4];
#pragma unroll
    for (int i = 0; i < 4; i++)
#pragma unroll
        for (int j = 0; j < 4; j++)
#pragma unroll
            for (int r = 0; r < 4; r++) acc[i][j][r] = 0.f;

    auto copy_chunk = [&](int c, int stg) {
        int k0 = c * KC;
        uint32_t base = sb + (uint32_t)stg * STAGE_B;
        const __nv_bfloat16* srcs[4] = { xhi, xlo, Bhi, Blo };
        int rows0[4] = { brow, brow, bcol, bcol };
#pragma unroll
        for (int t = 0; t < 4; t++) {
            const __nv_bfloat16* src = srcs[t] + (size_t)rows0[t] * GK + k0;
            uint32_t tb = base + (uint32_t)t * TILE_B;
#pragma unroll
            for (int i = 0; i < 2; i++) {
                int s = i * 256 + tid;
                int r = s >> 2, seg = s & 3;
                cp16(tb + (uint32_t)r * (RSTR * 2) + (uint32_t)seg * 16u,
                     src + (size_t)r * GK + seg * 8);
            }
        }
        CP_COMMIT();
    };

    GEMM_MAINLOOP(acc)

    __syncthreads();    // all warps done reading stage buffers before reuse

    // ------ fused epilogue: stage fp32 tile in smem, rotary+split, store ----
    float* ft = (float*)smem;    // [128][132] fp32
    int g = lane >> 2, t4 = lane & 3;
#pragma unroll
    for (int mi = 0; mi < 4; mi++) {
        int r0 = wm * 64 + mi * 16 + g;
#pragma unroll
        for (int ni = 0; ni < 4; ni++) {
            int cl = wn * 32 + ni * 8 + 2 * t4;
            float2 b01 = *(const float2*)&bias[bcol + cl];
            *(float2*)&ft[r0 * 132 + cl] =
                make_float2(acc[mi][ni][0] + b01.x, acc[mi][ni][1] + b01.y);
            *(float2*)&ft[(r0 + 8) * 132 + cl] =
                make_float2(acc[mi][ni][2] + b01.x, acc[mi][ni][3] + b01.y);
        }
    }
    __syncthreads();

    const bool  do_rot = (mtx < 2);
    const float scale  = (mtx == 0) ? 0.08838834764831845f : 1.0f;
    int d  = tid & 63;
    int rb = tid >> 6;
    float inv_freq = __expf(-(float)d * (9.210340371976184f / 64.0f));

    for (int rr = rb; rr < 128; rr += 4) {
        int grow = brow + rr;
        float a = ft[rr * 132 + d];
        float b2 = ft[rr * 132 + d + 64];
        float oa, ob2;
        if (do_rot) {
            int n = grow & (NSEQ - 1);
            float s, c;
            sincosf((float)n * inv_freq, &s, &c);
            oa  = (a * c - b2 * s) * scale;
            ob2 = (b2 * c + a * s) * scale;
        } else {
            oa = a; ob2 = b2;
        }
        size_t base = (size_t)grow * DMODEL + bcol + d;
        __nv_bfloat16 h = __float2bfloat16(oa);
        Oh[base] = h;
        Ol[base] = __float2bfloat16(oa - __bfloat162float(h));
        h = __float2bfloat16(ob2);
        Oh[base + 64] = h;
        Ol[base + 64] = __float2bfloat16(ob2 - __bfloat162float(h));
    }
}

// ---------------------------------------------------------------------------
// GEMM (3-pass split bf16), fp32 output + bias — out projection
// ---------------------------------------------------------------------------
__global__ __launch_bounds__(256)
void gemm_bf16x2(const __nv_bfloat16* __restrict__ Ahi, const __nv_bfloat16* __restrict__ Alo,
                 const __nv_bfloat16* __restrict__ Bhi, const __nv_bfloat16* __restrict__ Blo,
                 const float* __restrict__ bias, float* __restrict__ C)
{
    extern __shared__ __align__(128) char smem[];
    uint32_t sb = smem_u32(smem);
    const int tid  = threadIdx.x;
    const int wid  = tid >> 5;
    const int lane = tid & 31;
    const int brow = blockIdx.y * TM;
    const int bcol = blockIdx.x * TN;

    const int wm = wid & 1;
    const int wn = wid >> 1;

    float acc[4][4][4];
#pragma unroll
    for (int i = 0; i < 4; i++)
#pragma unroll
        for (int j = 0; j < 4; j++)
#pragma unroll
            for (int r = 0; r < 4; r++) acc[i][j][r] = 0.f;

    auto copy_chunk = [&](int c, int stg) {
        int k0 = c * KC;
        uint32_t base = sb + (uint32_t)stg * STAGE_B;
        const __nv_bfloat16* srcs[4] = { Ahi, Alo, Bhi, Blo };
        int rows0[4] = { brow, brow, bcol, bcol };
#pragma unroll
        for (int t = 0; t < 4; t++) {
            const __nv_bfloat16* src = srcs[t] + (size_t)rows0[t] * GK + k0;
            uint32_t tb = base + (uint32_t)t * TILE_B;
#pragma unroll
            for (int i = 0; i < 2; i++) {
                int s = i * 256 + tid;
                int r = s >> 2, seg = s & 3;
                cp16(tb + (uint32_t)r * (RSTR * 2) + (uint32_t)seg * 16u,
                     src + (size_t)r * GK + seg * 8);
            }
        }
        CP_COMMIT();
    };

    GEMM_MAINLOOP(acc)

    int g = lane >> 2, t4 = lane & 3;
#pragma unroll
    for (int mi = 0; mi < 4; mi++) {
        int r0 = brow + wm * 64 + mi * 16 + g;
#pragma unroll
        for (int ni = 0; ni < 4; ni++) {
            int col = bcol + wn * 32 + ni * 8 + 2 * t4;
            float2 b01 = *(const float2*)&bias[col];
            float2 o0, o1;
            o0.x = acc[mi][ni][0] + b01.x;
            o0.y = acc[mi][ni][1] + b01.y;
            o1.x = acc[mi][ni][2] + b01.x;
            o1.y = acc[mi][ni][3] + b01.y;
            *(float2*)&C[(size_t)r0 * DMODEL + col]       = o0;
            *(float2*)&C[(size_t)(r0 + 8) * DMODEL + col] = o1;
        }
    }
}

// ---------------------------------------------------------------------------
// Flash attention (causal), mma.sync split-bf16, BR=64, BC=32,
// double-buffered K/V (prefetch jt+1 overlaps compute jt), 128 threads.
// ---------------------------------------------------------------------------
#define BR 64
#define BC 32
#define QTILE_B  (64u * 272u)     // 17408
#define KVTILE_B (32u * 272u)     // 8704
#define ATT_SMEM (2u * QTILE_B + 8u * KVTILE_B)   // 104448

__global__ __launch_bounds__(128)
void flash_attn_mma(const __nv_bfloat16* __restrict__ qh, const __nv_bfloat16* __restrict__ ql,
                    const __nv_bfloat16* __restrict__ kh, const __nv_bfloat16* __restrict__ kl,
                    const __nv_bfloat16* __restrict__ vh, const __nv_bfloat16* __restrict__ vl,
                    __nv_bfloat16* __restrict__ oh, __nv_bfloat16* __restrict__ ol)
{
    extern __shared__ __align__(128) char smem[];
    uint32_t sb = smem_u32(smem);
    uint32_t sQh = sb, sQl = sb + QTILE_B;
    uint32_t sKV = sb + 2u * QTILE_B;   // [stage][Kh,Kl,Vh,Vl]

    const int tid  = threadIdx.x;
    const int warp = tid >> 5;
    const int lane = tid & 31;
    const int g    = lane >> 2;
    const int q4   = lane & 3;

    const int it = gridDim.x - 1 - blockIdx.x;   // heavy tiles first
    const int bh = blockIdx.y;
    const int b = bh >> 4, h = bh & 15;
    const int i0 = it * BR;

    const size_t hoff = (size_t)b * NSEQ * DMODEL + h * DHEAD;
    const __nv_bfloat16* qhb = qh + hoff;
    const __nv_bfloat16* qlb = ql + hoff;
    const __nv_bfloat16* khb = kh + hoff;
    const __nv_bfloat16* klb = kl + hoff;
    const __nv_bfloat16* vhb = vh + hoff;
    const __nv_bfloat16* vlb = vl + hoff;

    auto copyKV = [&](int jt, int stg) {
        int j0 = jt * BC;
        uint32_t base = sKV + (uint32_t)stg * 4u * KVTILE_B;
        const __nv_bfloat16* srcs[4] = { khb, klb, vhb, vlb };
#pragma unroll
        for (int t = 0; t < 4; t++)
#pragma unroll
            for (int i = 0; i < 4; i++) {
                int s = i * 128 + tid;
                int r = s >> 4, seg = s & 15;
                cp16(base + (uint32_t)t * KVTILE_B + (uint32_t)r * 272u + (uint32_t)seg * 16u,
                     srcs[t] + (size_t)(j0 + r) * DMODEL + seg * 8);
            }
        CP_COMMIT();
    };

    // preload Q (no commit — joins KV(0) group) then KV(0)
    {
        const __nv_bfloat16* srcs[2] = { qhb, qlb };
        uint32_t dsts[2] = { sQh, sQl };
#pragma unroll
        for (int t = 0; t < 2; t++)
#pragma unroll
            for (int i = 0; i < 8; i++) {
                int s = i * 128 + tid;
                int r = s >> 4, seg = s & 15;
                cp16(dsts[t] + (uint32_t)r * 272u + (uint32_t)seg * 16u,
                     srcs[t] + (size_t)(i0 + r) * DMODEL + seg * 8);
            }
    }
    copyKV(0, 0);

    float m0 = -1e30f, m1 = -1e30f, l0 = 0.f, l1 = 0.f;
    float oa[16][4];
#pragma unroll
    for (int d = 0; d < 16; d++)
#pragma unroll
        for (int r = 0; r < 4; r++) oa[d][r] = 0.f;

    const uint32_t lrow = (uint32_t)(lane & 15);
    const uint32_t lseg16 = (uint32_t)(lane >> 4) * 16u;

    const int NJT = it + 1;    // tiles 0..it (BR=2*BC: 2 K-tiles per q-tile step)
    for (int jt = 0; jt < 2 * NJT; jt++) {
        int stg = jt & 1;
        CP_WAIT(0);
        __syncthreads();
        if (jt + 1 < 2 * NJT) copyKV(jt + 1, stg ^ 1);

        int j0 = jt * BC;
        uint32_t kvb = sKV + (uint32_t)stg * 4u * KVTILE_B;
        uint32_t bKh = kvb, bKl = kvb + KVTILE_B;
        uint32_t bVh = kvb + 2u * KVTILE_B, bVl = kvb + 3u * KVTILE_B;

        // ---- S = Qh*Kh + Qh*Kl + Ql*Kh : s[4][4] (32 cols) ----
        float s[4][4];
#pragma unroll
        for (int nb = 0; nb < 4; nb++)
#pragma unroll
            for (int r = 0; r < 4; r++) s[nb][r] = 0.f;

        for (int kk = 0; kk < 8; kk++) {
            uint32_t qoff = ((uint32_t)(warp * 16) + lrow) * 272u + lseg16 + (uint32_t)kk * 32u;
            uint32_t Qh4[4], Ql4[4];
            ldmx4(sQh + qoff, Qh4[0], Qh4[1], Qh4[2], Qh4[3]);
            ldmx4(sQl + qoff, Ql4[0], Ql4[1], Ql4[2], Ql4[3]);
#pragma unroll
            for (int np = 0; np < 2; np++) {
                uint32_t koff = ((uint32_t)(np * 16) + lrow) * 272u + lseg16 + (uint32_t)kk * 32u;
                uint32_t h0, h1, h2, h3, l0r, l1r, l2r, l3r;
                ldmx4(bKh + koff, h0, h1, h2, h3);
                ldmx4(bKl + koff, l0r, l1r, l2r, l3r);
                int nb = np * 2;
                mma16816(s[nb][0], s[nb][1], s[nb][2], s[nb][3],
                         Qh4[0], Qh4[1], Qh4[2], Qh4[3], h0, h2);
                mma16816(s[nb][0], s[nb][1], s[nb][2], s[nb][3],
                         Qh4[0], Qh4[1], Qh4[2], Qh4[3], l0r, l2r);
                mma16816(s[nb][0], s[nb][1], s[nb][2], s[nb][3],
                         Ql4[0], Ql4[1], Ql4[2], Ql4[3], h0, h2);
                mma16816(s[nb + 1][0], s[nb + 1][1], s[nb + 1][2], s[nb + 1][3],
                         Qh4[0], Qh4[1], Qh4[2], Qh4[3], h1, h3);
                mma16816(s[nb + 1][0], s[nb + 1][1], s[nb + 1][2], s[nb + 1][3],
                         Qh4[0], Qh4[1], Qh4[2], Qh4[3], l1r, l3r);
                mma16816(s[nb + 1][0], s[nb + 1][1], s[nb + 1][2], s[nb + 1][3],
                         Ql4[0], Ql4[1], Ql4[2], Ql4[3], h1, h3);
            }
        }

        // ---- causal mask (tiles overlapping the diagonal) ----
        if (j0 + BC > i0 + warp * 16) {   // only needed when this warp's rows may be exceeded
            int r0 = i0 + warp * 16 + g;
            int r1 = r0 + 8;
#pragma unroll
            for (int nb = 0; nb < 4; nb++) {
                int c0 = j0 + nb * 8 + 2 * q4;
                if (c0 > r0)     s[nb][0] = -1e30f;
                if (c0 + 1 > r0) s[nb][1] = -1e30f;
                if (c0 > r1)     s[nb][2] = -1e30f;
                if (c0 + 1 > r1) s[nb][3] = -1e30f;
            }
        }

        // ---- online softmax ----
        float mx0 = -1e30f, mx1 = -1e30f;
#pragma unroll
        for (int nb = 0; nb < 4; nb++) {
            mx0 = fmaxf(mx0, fmaxf(s[nb][0], s[nb][1]));
            mx1 = fmaxf(mx1, fmaxf(s[nb][2], s[nb][3]));
        }
        mx0 = fmaxf(mx0, __shfl_xor_sync(0xffffffffu, mx0, 1));
        mx0 = fmaxf(mx0, __shfl_xor_sync(0xffffffffu, mx0, 2));
        mx1 = fmaxf(mx1, __shfl_xor_sync(0xffffffffu, mx1, 1));
        mx1 = fmaxf(mx1, __shfl_xor_sync(0xffffffffu, mx1, 2));

        float m0n = fmaxf(m0, mx0), m1n = fmaxf(m1, mx1);
        float f0 = __expf(m0 - m0n), f1 = __expf(m1 - m1n);

        float sum0 = 0.f, sum1 = 0.f;
#pragma unroll
        for (int nb = 0; nb < 4; nb++) {
            s[nb][0] = __expf(s[nb][0] - m0n);
            s[nb][1] = __expf(s[nb][1] - m0n);
            s[nb][2] = __expf(s[nb][2] - m1n);
            s[nb][3] = __expf(s[nb][3] - m1n);
            sum0 += s[nb][0] + s[nb][1];
            sum1 += s[nb][2] + s[nb][3];
        }
        sum0 += __shfl_xor_sync(0xffffffffu, sum0, 1);
        sum0 += __shfl_xor_sync(0xffffffffu, sum0, 2);
        sum1 += __shfl_xor_sync(0xffffffffu, sum1, 1);
        sum1 += __shfl_xor_sync(0xffffffffu, sum1, 2);

        m0 = m0n; m1 = m1n;
        l0 = l0 * f0 + sum0;
        l1 = l1 * f1 + sum1;

#pragma unroll
        for (int d = 0; d < 16; d++) {
            oa[d][0] *= f0; oa[d][1] *= f0;
            oa[d][2] *= f1; oa[d][3] *= f1;
        }

        // ---- P -> bf16 hi/lo A-frags ----
        uint32_t Ph[2][4], Pl[2][4];
#pragma unroll
        for (int kk2 = 0; kk2 < 2; kk2++) {
            int nb = 2 * kk2;
#pragma unroll
            for (int half = 0; half < 2; half++) {
                int src = nb + half;
                float p0 = s[src][0], p1 = s[src][1], p2 = s[src][2], p3 = s[src][3];
                __nv_bfloat162 hA = __floats2bfloat162_rn(p0, p1);
                __nv_bfloat162 hB = __floats2bfloat162_rn(p2, p3);
                Ph[kk2][half * 2 + 0] = *(uint32_t*)&hA;
                Ph[kk2][half * 2 + 1] = *(uint32_t*)&hB;
                Pl[kk2][half * 2 + 0] = packbf(p0 - __bfloat162float(__low2bfloat16(hA)),
                                               p1 - __bfloat162float(__high2bfloat16(hA)));
                Pl[kk2][half * 2 + 1] = packbf(p2 - __bfloat162float(__low2bfloat16(hB)),
                                               p3 - __bfloat162float(__high2bfloat16(hB)));
            }
        }

        // ---- O += Ph*Vh + Ph*Vl + Pl*Vh ----
#pragma unroll
        for (int kk2 = 0; kk2 < 2; kk2++) {
#pragma unroll
            for (int dp = 0; dp < 8; dp++) {
                uint32_t voff = ((uint32_t)(kk2 * 16) + lrow) * 272u
                              + (uint32_t)dp * 32u + (uint32_t)(lane >> 4) * 16u;
                uint32_t h0, h1, h2, h3, l0r, l1r, l2r, l3r;
                ldmx4t(bVh + voff, h0, h1, h2, h3);
                ldmx4t(bVl + voff, l0r, l1r, l2r, l3r);
                int dnb = dp * 2;
                mma16816(oa[dnb][0], oa[dnb][1], oa[dnb][2], oa[dnb][3],
                         Ph[kk2][0], Ph[kk2][1], Ph[kk2][2], Ph[kk2][3], h0, h1);
                mma16816(oa[dnb][0], oa[dnb][1], oa[dnb][2], oa[dnb][3],
                         Ph[kk2][0], Ph[kk2][1], Ph[kk2][2], Ph[kk2][3], l0r, l1r);
                mma16816(oa[dnb][0], oa[dnb][1], oa[dnb][2], oa[dnb][3],
                         Pl[kk2][0], Pl[kk2][1], Pl[kk2][2], Pl[kk2][3], h0, h1);
                mma16816(oa[dnb + 1][0], oa[dnb + 1][1], oa[dnb + 1][2], oa[dnb + 1][3],
                         Ph[kk2][0], Ph[kk2][1], Ph[kk2][2], Ph[kk2][3], h2, h3);
                mma16816(oa[dnb + 1][0], oa[dnb + 1][1], oa[dnb + 1][2], oa[dnb + 1][3],
                         Ph[kk2][0], Ph[kk2][1], Ph[kk2][2], Ph[kk2][3], l2r, l3r);
                mma16816(oa[dnb + 1][0], oa[dnb + 1][1], oa[dnb + 1][2], oa[dnb + 1][3],
                         Pl[kk2][0], Pl[kk2][1], Pl[kk2][2], Pl[kk2][3], h2, h3);
            }
        }
    }

    // ---- epilogue: normalize, split to bf16 hi/lo ----
    float inv0 = 1.0f / l0, inv1 = 1.0f / l1;
    int r0 = i0 + warp * 16 + g;
    __nv_bfloat16* ohb = oh + hoff;
    __nv_bfloat16* olb = ol + hoff;
#pragma unroll
    for (int dnb = 0; dnb < 16; dnb++) {
        int col = dnb * 8 + 2 * q4;
        float a0 = oa[dnb][0] * inv0, a1 = oa[dnb][1] * inv0;
        float b0 = oa[dnb][2] * inv1, b1 = oa[dnb][3] * inv1;
        __nv_bfloat162 h0 = __floats2bfloat162_rn(a0, a1);
        __nv_bfloat162 h1 = __floats2bfloat162_rn(b0, b1);
        *(__nv_bfloat162*)&ohb[(size_t)r0 * DMODEL + col] = h0;
        *(__nv_bfloat162*)&ohb[(size_t)(r0 + 8) * DMODEL + col] = h1;
        __nv_bfloat162 lo0, lo1;
        lo0 = __floats2bfloat162_rn(a0 - __bfloat162float(__low2bfloat16(h0)),
                                    a1 - __bfloat162float(__high2bfloat16(h0)));
        lo1 = __floats2bfloat162_rn(b0 - __bfloat162float(__low2bfloat16(h1)),
                                    b1 - __bfloat162float(__high2bfloat16(h1)));
        *(__nv_bfloat162*)&olb[(size_t)r0 * DMODEL + col] = lo0;
        *(__nv_bfloat162*)&olb[(size_t)(r0 + 8) * DMODEL + col] = lo1;
    }
}

// ---------------------------------------------------------------------------
extern "C" void kernel_launch(void* const* d_in, const int* in_sizes, int n_in,
                              void* d_out, int out_size)
{
    const float* x  = (const float*)d_in[0];
    const float* Wq = (const float*)d_in[1];
    const float* bq = (const float*)d_in[2];
    const float* Wk = (const float*)d_in[3];
    const float* bk = (const float*)d_in[4];
    const float* Wv = (const float*)d_in[5];
    const float* bv = (const float*)d_in[6];
    const float* Wo = (const float*)d_in[7];
    const float* bo = (const float*)d_in[8];
    float* out = (float*)d_out;

    __nv_bfloat16 *xhi, *xlo, *ahi, *alo, *qhh, *qll, *khh, *kll, *vhh, *vll;
    __nv_bfloat16 *wqh, *wql, *wkh, *wkl, *wvh, *wvl, *woh, *wol;
    cudaGetSymbolAddress((void**)&xhi, g_xhi);
    cudaGetSymbolAddress((void**)&xlo, g_xlo);
    cudaGetSymbolAddress((void**)&ahi, g_ahi);
    cudaGetSymbolAddress((void**)&alo, g_alo);
    cudaGetSymbolAddress((void**)&qhh, g_qh);
    cudaGetSymbolAddress((void**)&qll, g_ql);
    cudaGetSymbolAddress((void**)&khh, g_kh);
    cudaGetSymbolAddress((void**)&kll, g_kl);
    cudaGetSymbolAddress((void**)&vhh, g_vh);
    cudaGetSymbolAddress((void**)&vll, g_vl);
    cudaGetSymbolAddress((void**)&wqh, g_wq_hi);
    cudaGetSymbolAddress((void**)&wql, g_wq_lo);
    cudaGetSymbolAddress((void**)&wkh, g_wk_hi);
    cudaGetSymbolAddress((void**)&wkl, g_wk_lo);
    cudaGetSymbolAddress((void**)&wvh, g_wv_hi);
    cudaGetSymbolAddress((void**)&wvl, g_wv_lo);
    cudaGetSymbolAddress((void**)&woh, g_wo_hi);
    cudaGetSymbolAddress((void**)&wol, g_wo_lo);

    cudaFuncSetAttribute(gemm_qkv, cudaFuncAttributeMaxDynamicSharedMemorySize, GEMM_SMEM);
    cudaFuncSetAttribute(gemm_bf16x2, cudaFuncAttributeMaxDynamicSharedMemorySize, GEMM_SMEM);
    cudaFuncSetAttribute(flash_attn_mma, cudaFuncAttributeMaxDynamicSharedMemorySize, ATT_SMEM);

    // prep: split x, transpose+split weights
    int n4x = ROWS * DMODEL / 4;
    split_kernel<<<(n4x + 255) / 256, 256>>>((const float4*)x, xhi, xlo, n4x);
    dim3 tgrid(DMODEL / 32, DMODEL / 32);
    transpose_split<<<tgrid, 256>>>(Wq, wqh, wql);
    transpose_split<<<tgrid, 256>>>(Wk, wkh, wkl);
    transpose_split<<<tgrid, 256>>>(Wv, wvh, wvl);
    transpose_split<<<tgrid, 256>>>(Wo, woh, wol);

    // fused QKV projection + rotary + split
    dim3 qkv_grid(3 * DMODEL / TN, ROWS / TM);   // (48, 32)
    gemm_qkv<<<qkv_grid, 256, GEMM_SMEM>>>(xhi, xlo, wqh, wql, wkh, wkl, wvh, wvl,
                                           bq, bk, bv, qhh, qll, khh, kll, vhh, vll);

    // tensor-core flash attention (emits bf16 hi/lo)
    dim3 attn_grid(NSEQ / BR, BATCH * HEADS);   // (32, 32)
    flash_attn_mma<<<attn_grid, 128, ATT_SMEM>>>(qhh, qll, khh, kll, vhh, vll, ahi, alo);

    // output projection
    dim3 ggrid(DMODEL / TN, ROWS / TM);   // (16, 32)
    gemm_bf16x2<<<ggrid, 256, GEMM_SMEM>>>(ahi, alo, woh, wol, bo, out);
}

// round 7
// speedup vs baseline: 1.0300x; 1.0300x over previous
#include <cuda_runtime.h>
#include <cuda_bf16.h>
#include <math.h>
#include <stdint.h>

#define BATCH 2
#define NSEQ  2048
#define DMODEL 2048
#define HEADS 16
#define DHEAD 128
#define ROWS (BATCH*NSEQ)   // 4096

// ---------------------------------------------------------------------------
// scratch (device globals: no allocation allowed)
// ---------------------------------------------------------------------------
__device__ __nv_bfloat16 g_xhi[ROWS*DMODEL];
__device__ __nv_bfloat16 g_xlo[ROWS*DMODEL];
__device__ __nv_bfloat16 g_ahi[ROWS*DMODEL];
__device__ __nv_bfloat16 g_alo[ROWS*DMODEL];
__device__ __nv_bfloat16 g_qh[ROWS*DMODEL];
__device__ __nv_bfloat16 g_ql[ROWS*DMODEL];
__device__ __nv_bfloat16 g_kh[ROWS*DMODEL];
__device__ __nv_bfloat16 g_kl[ROWS*DMODEL];
__device__ __nv_bfloat16 g_vh[ROWS*DMODEL];
__device__ __nv_bfloat16 g_vl[ROWS*DMODEL];
__device__ __nv_bfloat16 g_wq_hi[DMODEL*DMODEL];
__device__ __nv_bfloat16 g_wq_lo[DMODEL*DMODEL];
__device__ __nv_bfloat16 g_wk_hi[DMODEL*DMODEL];
__device__ __nv_bfloat16 g_wk_lo[DMODEL*DMODEL];
__device__ __nv_bfloat16 g_wv_hi[DMODEL*DMODEL];
__device__ __nv_bfloat16 g_wv_lo[DMODEL*DMODEL];
__device__ __nv_bfloat16 g_wo_hi[DMODEL*DMODEL];
__device__ __nv_bfloat16 g_wo_lo[DMODEL*DMODEL];

// ---------------------------------------------------------------------------
// helpers
// ---------------------------------------------------------------------------
__device__ __forceinline__ uint32_t smem_u32(const void* p) {
    uint32_t a;
    asm("{ .reg .u64 t; cvta.to.shared.u64 t, %1; cvt.u32.u64 %0, t; }" : "=r"(a) : "l"(p));
    return a;
}

__device__ __forceinline__ void cp16(uint32_t dst, const void* src) {
    asm volatile("cp.async.cg.shared.global [%0], [%1], 16;" :: "r"(dst), "l"(src));
}
#define CP_COMMIT() asm volatile("cp.async.commit_group;" ::: "memory")
#define CP_WAIT(n)  asm volatile("cp.async.wait_group %0;" :: "n"(n) : "memory")

__device__ __forceinline__ void ldmx4(uint32_t addr, uint32_t& r0, uint32_t& r1,
                                      uint32_t& r2, uint32_t& r3) {
    asm volatile("ldmatrix.sync.aligned.m8n8.x4.shared.b16 {%0,%1,%2,%3}, [%4];"
                 : "=r"(r0), "=r"(r1), "=r"(r2), "=r"(r3) : "r"(addr));
}
__device__ __forceinline__ void ldmx4t(uint32_t addr, uint32_t& r0, uint32_t& r1,
                                       uint32_t& r2, uint32_t& r3) {
    asm volatile("ldmatrix.sync.aligned.m8n8.x4.trans.shared.b16 {%0,%1,%2,%3}, [%4];"
                 : "=r"(r0), "=r"(r1), "=r"(r2), "=r"(r3) : "r"(addr));
}

__device__ __forceinline__ void mma16816(float& c0, float& c1, float& c2, float& c3,
                                         uint32_t a0, uint32_t a1, uint32_t a2, uint32_t a3,
                                         uint32_t b0, uint32_t b1) {
    asm volatile(
        "mma.sync.aligned.m16n8k16.row.col.f32.bf16.bf16.f32 "
        "{%0,%1,%2,%3}, {%4,%5,%6,%7}, {%8,%9}, {%0,%1,%2,%3};"
        : "+f"(c0), "+f"(c1), "+f"(c2), "+f"(c3)
        : "r"(a0), "r"(a1), "r"(a2), "r"(a3), "r"(b0), "r"(b1));
}

__device__ __forceinline__ uint32_t packbf(float a, float b) {
    __nv_bfloat162 t = __floats2bfloat162_rn(a, b);
    return *(uint32_t*)&t;
}

// ---------------------------------------------------------------------------
// split: fp32 -> (hi, lo) bf16 pair
// ---------------------------------------------------------------------------
__global__ __launch_bounds__(256)
void split_kernel(const float4* __restrict__ in, __nv_bfloat16* __restrict__ hi,
                  __nv_bfloat16* __restrict__ lo, int n4)
{
    int i = blockIdx.x * 256 + threadIdx.x;
    if (i >= n4) return;
    float4 v = in[i];
    __nv_bfloat16 h0 = __float2bfloat16(v.x);
    __nv_bfloat16 h1 = __float2bfloat16(v.y);
    __nv_bfloat16 h2 = __float2bfloat16(v.z);
    __nv_bfloat16 h3 = __float2bfloat16(v.w);
    __nv_bfloat162* hp = (__nv_bfloat162*)(hi + 4 * (size_t)i);
    hp[0] = __nv_bfloat162(h0, h1);
    hp[1] = __nv_bfloat162(h2, h3);
    __nv_bfloat162* lp = (__nv_bfloat162*)(lo + 4 * (size_t)i);
    lp[0] = __nv_bfloat162(__float2bfloat16(v.x - __bfloat162float(h0)),
                           __float2bfloat16(v.y - __bfloat162float(h1)));
    lp[1] = __nv_bfloat162(__float2bfloat16(v.z - __bfloat162float(h2)),
                           __float2bfloat16(v.w - __bfloat162float(h3)));
}

// ---------------------------------------------------------------------------
// transpose + split, all 4 weights in one launch (blockIdx.z selects)
// ---------------------------------------------------------------------------
__global__ __launch_bounds__(256)
void transpose_split4(const float* __restrict__ W0, const float* __restrict__ W1,
                      const float* __restrict__ W2, const float* __restrict__ W3,
                      __nv_bfloat16* __restrict__ th0, __nv_bfloat16* __restrict__ tl0,
                      __nv_bfloat16* __restrict__ th1, __nv_bfloat16* __restrict__ tl1,
                      __nv_bfloat16* __restrict__ th2, __nv_bfloat16* __restrict__ tl2,
                      __nv_bfloat16* __restrict__ th3, __nv_bfloat16* __restrict__ tl3)
{
    int z = blockIdx.z;
    const float* W = (z == 0) ? W0 : (z == 1) ? W1 : (z == 2) ? W2 : W3;
    __nv_bfloat16* th = (z == 0) ? th0 : (z == 1) ? th1 : (z == 2) ? th2 : th3;
    __nv_bfloat16* tl = (z == 0) ? tl0 : (z == 1) ? tl1 : (z == 2) ? tl2 : tl3;

    __shared__ float t[32][33];
    int n0 = blockIdx.x * 32, k0 = blockIdx.y * 32;
    int tx = threadIdx.x & 31, ty = threadIdx.x >> 5;   // 32 x 8
#pragma unroll
    for (int i = 0; i < 32; i += 8)
        t[ty + i][tx] = W[(size_t)(k0 + ty + i) * DMODEL + n0 + tx];
    __syncthreads();
#pragma unroll
    for (int i = 0; i < 32; i += 8) {
        float v = t[tx][ty + i];
        __nv_bfloat16 h = __float2bfloat16(v);
        size_t o = (size_t)(n0 + ty + i) * DMODEL + k0 + tx;
        th[o] = h;
        tl[o] = __float2bfloat16(v - __bfloat162float(h));
    }
}

// ---------------------------------------------------------------------------
// GEMM tiles / pipeline config
// ---------------------------------------------------------------------------
#define GK DMODEL
#define TM 128
#define TN 128
#define KC 32
#define RSTR 40
#define TILE_B (128u * RSTR * 2u)
#define STAGE_B (4u * TILE_B)
#define GEMM_SMEM (2u * STAGE_B)     // 81920 B

// R5 mainloop: copy(c+1) issued BEFORE wait -> deepest prefetch; 2 syncs/chunk
#define GEMM_MAINLOOP(ACC)                                                              \
    const int NCH = GK / KC;                                                            \
    copy_chunk(0, 0);                                                                   \
    const uint32_t lrow = (uint32_t)(lane & 15);                                        \
    const uint32_t lcol = (uint32_t)((lane >> 4) & 1) * 8u;                             \
    for (int c = 0; c < NCH; c++) {                                                     \
        int stg = c & 1;                                                                \
        if (c + 1 < NCH) {                                                              \
            copy_chunk(c + 1, stg ^ 1);                                                 \
            CP_WAIT(1);                                                                 \
        } else {                                                                        \
            CP_WAIT(0);                                                                 \
        }                                                                               \
        __syncthreads();                                                                \
        uint32_t base = sb + (uint32_t)stg * STAGE_B;                                   \
        uint32_t ah_b = base;                                                           \
        uint32_t al_b = base + TILE_B;                                                  \
        uint32_t bh_b = base + 2u * TILE_B;                                             \
        uint32_t bl_b = base + 3u * TILE_B;                                             \
        _Pragma("unroll")                                                               \
        for (int kk = 0; kk < 2; kk++) {                                                \
            uint32_t koff = (uint32_t)(kk * 16) * 2u + lcol * 2u;                       \
            uint32_t Ah[4][4], Al[4][4];                                                \
            _Pragma("unroll")                                                           \
            for (int mi = 0; mi < 4; mi++) {                                            \
                uint32_t roff = ((uint32_t)(wm * 64 + mi * 16) + lrow) * (RSTR * 2u) + koff; \
                ldmx4(ah_b + roff, Ah[mi][0], Ah[mi][1], Ah[mi][2], Ah[mi][3]);         \
                ldmx4(al_b + roff, Al[mi][0], Al[mi][1], Al[mi][2], Al[mi][3]);         \
            }                                                                           \
            uint32_t Bh[4][2], Bl[4][2];                                                \
            _Pragma("unroll")                                                           \
            for (int np = 0; np < 2; np++) {                                            \
                uint32_t roff = ((uint32_t)(wn * 32 + np * 16) + lrow) * (RSTR * 2u) + koff; \
                uint32_t r0, r1, r2, r3;                                                \
                ldmx4(bh_b + roff, r0, r1, r2, r3);                                     \
                Bh[np * 2][0] = r0; Bh[np * 2 + 1][0] = r1;                             \
                Bh[np * 2][1] = r2; Bh[np * 2 + 1][1] = r3;                             \
                ldmx4(bl_b + roff, r0, r1, r2, r3);                                     \
                Bl[np * 2][0] = r0; Bl[np * 2 + 1][0] = r1;                             \
                Bl[np * 2][1] = r2; Bl[np * 2 + 1][1] = r3;                             \
            }                                                                           \
            _Pragma("unroll")                                                           \
            for (int mi = 0; mi < 4; mi++)                                              \
                _Pragma("unroll")                                                       \
                for (int ni = 0; ni < 4; ni++) {                                        \
                    mma16816(ACC[mi][ni][0], ACC[mi][ni][1], ACC[mi][ni][2], ACC[mi][ni][3], \
                             Ah[mi][0], Ah[mi][1], Ah[mi][2], Ah[mi][3],                \
                             Bh[ni][0], Bh[ni][1]);                                     \
                    mma16816(ACC[mi][ni][0], ACC[mi][ni][1], ACC[mi][ni][2], ACC[mi][ni][3], \
                             Ah[mi][0], Ah[mi][1], Ah[mi][2], Ah[mi][3],                \
                             Bl[ni][0], Bl[ni][1]);                                     \
                    mma16816(ACC[mi][ni][0], ACC[mi][ni][1], ACC[mi][ni][2], ACC[mi][ni][3], \
                             Al[mi][0], Al[mi][1], Al[mi][2], Al[mi][3],                \
                             Bh[ni][0], Bh[ni][1]);                                     \
                }                                                                       \
        }                                                                               \
        __syncthreads();                                                                \
    }

// ---------------------------------------------------------------------------
// Fused QKV GEMM + rotary + bf16 split epilogue. grid (48, 32).
// ---------------------------------------------------------------------------
__global__ __launch_bounds__(256)
void gemm_qkv(const __nv_bfloat16* __restrict__ xhi, const __nv_bfloat16* __restrict__ xlo,
              const __nv_bfloat16* __restrict__ wqh, const __nv_bfloat16* __restrict__ wql,
              const __nv_bfloat16* __restrict__ wkh, const __nv_bfloat16* __restrict__ wkl,
              const __nv_bfloat16* __restrict__ wvh, const __nv_bfloat16* __restrict__ wvl,
              const float* __restrict__ bq, const float* __restrict__ bk,
              const float* __restrict__ bv,
              __nv_bfloat16* __restrict__ qh, __nv_bfloat16* __restrict__ ql,
              __nv_bfloat16* __restrict__ kh, __nv_bfloat16* __restrict__ kl,
              __nv_bfloat16* __restrict__ vh, __nv_bfloat16* __restrict__ vl)
{
    extern __shared__ __align__(128) char smem[];
    uint32_t sb = smem_u32(smem);
    const int tid  = threadIdx.x;
    const int wid  = tid >> 5;
    const int lane = tid & 31;
    const int brow = blockIdx.y * TM;
    const int mtx  = blockIdx.x >> 4;            // 0=q, 1=k, 2=v
    const int bcol = (blockIdx.x & 15) * TN;

    const __nv_bfloat16* Bhi = (mtx == 0) ? wqh : (mtx == 1) ? wkh : wvh;
    const __nv_bfloat16* Blo = (mtx == 0) ? wql : (mtx == 1) ? wkl : wvl;
    const float* bias        = (mtx == 0) ? bq  : (mtx == 1) ? bk  : bv;
    __nv_bfloat16* Oh        = (mtx == 0) ? qh  : (mtx == 1) ? kh  : vh;
    __nv_bfloat16* Ol        = (mtx == 0) ? ql  : (mtx == 1) ? kl  : vl;

    const int wm = wid & 1;
    const int wn = wid >> 1;

    float acc[4][4][4];
#pragma unroll
    for (int i = 0; i < 4; i++)
#pragma unroll
        for (int j = 0; j < 4; j++)
#pragma unroll
            for (int r = 0; r < 4; r++) acc[i][j][r] = 0.f;

    auto copy_chunk = [&](int c, int stg) {
        int k0 = c * KC;
        uint32_t base = sb + (uint32_t)stg * STAGE_B;
        const __nv_bfloat16* srcs[4] = { xhi, xlo, Bhi, Blo };
        int rows0[4] = { brow, brow, bcol, bcol };
#pragma unroll
        for (int t = 0; t < 4; t++) {
            const __nv_bfloat16* src = srcs[t] + (size_t)rows0[t] * GK + k0;
            uint32_t tb = base + (uint32_t)t * TILE_B;
#pragma unroll
            for (int i = 0; i < 2; i++) {
                int s = i * 256 + tid;
                int r = s >> 2, seg = s & 3;
                cp16(tb + (uint32_t)r * (RSTR * 2) + (uint32_t)seg * 16u,
                     src + (size_t)r * GK + seg * 8);
            }
        }
        CP_COMMIT();
    };

    GEMM_MAINLOOP(acc)

    // ------ fused epilogue: stage fp32 tile in smem, rotary+split, store ----
    float* ft = (float*)smem;    // [128][132] fp32
    int g = lane >> 2, t4 = lane & 3;
#pragma unroll
    for (int mi = 0; mi < 4; mi++) {
        int r0 = wm * 64 + mi * 16 + g;
#pragma unroll
        for (int ni = 0; ni < 4; ni++) {
            int cl = wn * 32 + ni * 8 + 2 * t4;
            float2 b01 = *(const float2*)&bias[bcol + cl];
            *(float2*)&ft[r0 * 132 + cl] =
                make_float2(acc[mi][ni][0] + b01.x, acc[mi][ni][1] + b01.y);
            *(float2*)&ft[(r0 + 8) * 132 + cl] =
                make_float2(acc[mi][ni][2] + b01.x, acc[mi][ni][3] + b01.y);
        }
    }
    __syncthreads();

    const bool  do_rot = (mtx < 2);
    const float scale  = (mtx == 0) ? 0.08838834764831845f : 1.0f;
    int d  = tid & 63;
    int rb = tid >> 6;
    float inv_freq = __expf(-(float)d * (9.210340371976184f / 64.0f));

    for (int rr = rb; rr < 128; rr += 4) {
        int grow = brow + rr;
        float a = ft[rr * 132 + d];
        float b2 = ft[rr * 132 + d + 64];
        float oa, ob2;
        if (do_rot) {
            int n = grow & (NSEQ - 1);
            float s, c;
            sincosf((float)n * inv_freq, &s, &c);
            oa  = (a * c - b2 * s) * scale;
            ob2 = (b2 * c + a * s) * scale;
        } else {
            oa = a; ob2 = b2;
        }
        size_t base = (size_t)grow * DMODEL + bcol + d;
        __nv_bfloat16 h = __float2bfloat16(oa);
        Oh[base] = h;
        Ol[base] = __float2bfloat16(oa - __bfloat162float(h));
        h = __float2bfloat16(ob2);
        Oh[base + 64] = h;
        Ol[base + 64] = __float2bfloat16(ob2 - __bfloat162float(h));
    }
}

// ---------------------------------------------------------------------------
// GEMM (3-pass split bf16), fp32 output + bias — out projection
// ---------------------------------------------------------------------------
__global__ __launch_bounds__(256)
void gemm_bf16x2(const __nv_bfloat16* __restrict__ Ahi, const __nv_bfloat16* __restrict__ Alo,
                 const __nv_bfloat16* __restrict__ Bhi, const __nv_bfloat16* __restrict__ Blo,
                 const float* __restrict__ bias, float* __restrict__ C)
{
    extern __shared__ __align__(128) char smem[];
    uint32_t sb = smem_u32(smem);
    const int tid  = threadIdx.x;
    const int wid  = tid >> 5;
    const int lane = tid & 31;
    const int brow = blockIdx.y * TM;
    const int bcol = blockIdx.x * TN;

    const int wm = wid & 1;
    const int wn = wid >> 1;

    float acc[4][4][4];
#pragma unroll
    for (int i = 0; i < 4; i++)
#pragma unroll
        for (int j = 0; j < 4; j++)
#pragma unroll
            for (int r = 0; r < 4; r++) acc[i][j][r] = 0.f;

    auto copy_chunk = [&](int c, int stg) {
        int k0 = c * KC;
        uint32_t base = sb + (uint32_t)stg * STAGE_B;
        const __nv_bfloat16* srcs[4] = { Ahi, Alo, Bhi, Blo };
        int rows0[4] = { brow, brow, bcol, bcol };
#pragma unroll
        for (int t = 0; t < 4; t++) {
            const __nv_bfloat16* src = srcs[t] + (size_t)rows0[t] * GK + k0;
            uint32_t tb = base + (uint32_t)t * TILE_B;
#pragma unroll
            for (int i = 0; i < 2; i++) {
                int s = i * 256 + tid;
                int r = s >> 2, seg = s & 3;
                cp16(tb + (uint32_t)r * (RSTR * 2) + (uint32_t)seg * 16u,
                     src + (size_t)r * GK + seg * 8);
            }
        }
        CP_COMMIT();
    };

    GEMM_MAINLOOP(acc)

    int g = lane >> 2, t4 = lane & 3;
#pragma unroll
    for (int mi = 0; mi < 4; mi++) {
        int r0 = brow + wm * 64 + mi * 16 + g;
#pragma unroll
        for (int ni = 0; ni < 4; ni++) {
            int col = bcol + wn * 32 + ni * 8 + 2 * t4;
            float2 b01 = *(const float2*)&bias[col];
            float2 o0, o1;
            o0.x = acc[mi][ni][0] + b01.x;
            o0.y = acc[mi][ni][1] + b01.y;
            o1.x = acc[mi][ni][2] + b01.x;
            o1.y = acc[mi][ni][3] + b01.y;
            *(float2*)&C[(size_t)r0 * DMODEL + col]       = o0;
            *(float2*)&C[(size_t)(r0 + 8) * DMODEL + col] = o1;
        }
    }
}

// ---------------------------------------------------------------------------
// Flash attention (causal), BR=BC=64, 128 threads. Q frags hoisted to regs.
// 3 rotating smem buffers (34816B each): K prefetch overlaps S-phase,
// V prefetch overlaps PV-phase. 104448B smem -> 2 CTAs/SM.
// ---------------------------------------------------------------------------
#define ABUF_B 34816u                 // one (hi,lo) 64x256B pair at 272B stride
#define ATT_SMEM (3u * ABUF_B)        // 104448

__global__ __launch_bounds__(128)
void flash_attn_mma(const __nv_bfloat16* __restrict__ qh, const __nv_bfloat16* __restrict__ ql,
                    const __nv_bfloat16* __restrict__ kh, const __nv_bfloat16* __restrict__ kl,
                    const __nv_bfloat16* __restrict__ vh, const __nv_bfloat16* __restrict__ vl,
                    __nv_bfloat16* __restrict__ oh, __nv_bfloat16* __restrict__ ol)
{
    extern __shared__ __align__(128) char smem[];
    uint32_t sb = smem_u32(smem);

    const int tid  = threadIdx.x;
    const int warp = tid >> 5;
    const int lane = tid & 31;
    const int g    = lane >> 2;
    const int q4   = lane & 3;

    const int it = gridDim.x - 1 - blockIdx.x;   // heavy tiles first
    const int bh = blockIdx.y;
    const int b = bh >> 4, h = bh & 15;
    const int i0 = it * 64;

    const size_t hoff = (size_t)b * NSEQ * DMODEL + h * DHEAD;
    const __nv_bfloat16* qhb = qh + hoff;
    const __nv_bfloat16* qlb = ql + hoff;
    const __nv_bfloat16* khb = kh + hoff;
    const __nv_bfloat16* klb = kl + hoff;
    const __nv_bfloat16* vhb = vh + hoff;
    const __nv_bfloat16* vlb = vl + hoff;

    // copy one (hi,lo) 64-row pair into buffer, one commit group
    auto copyPair = [&](const __nv_bfloat16* srcH, const __nv_bfloat16* srcL,
                        int row0, uint32_t buf) {
#pragma unroll
        for (int i = 0; i < 8; i++) {
            int s = i * 128 + tid;
            int r = s >> 4, seg = s & 15;
            uint32_t off = (uint32_t)r * 272u + (uint32_t)seg * 16u;
            cp16(buf + off,          srcH + (size_t)(row0 + r) * DMODEL + seg * 8);
            cp16(buf + 17408u + off, srcL + (size_t)(row0 + r) * DMODEL + seg * 8);
        }
        CP_COMMIT();
    };

    uint32_t b0 = sb, b1 = sb + ABUF_B, b2 = sb + 2u * ABUF_B;

    copyPair(qhb, qlb, i0, b0);   // group: Q
    copyPair(khb, klb, 0,  b1);   // group: K(0)
    copyPair(vhb, vlb, 0,  b2);   // group: V(0)

    CP_WAIT(2);                   // Q done; K0,V0 may be in flight
    __syncthreads();

    // ---- hoist Q fragments (loop-invariant) into registers ----
    const uint32_t lrow = (uint32_t)(lane & 15);
    const uint32_t lseg16 = (uint32_t)(lane >> 4) * 16u;
    uint32_t Qh4[8][4], Ql4[8][4];
#pragma unroll
    for (int kk = 0; kk < 8; kk++) {
        uint32_t qoff = ((uint32_t)(warp * 16) + lrow) * 272u + lseg16 + (uint32_t)kk * 32u;
        ldmx4(b0 + qoff,          Qh4[kk][0], Qh4[kk][1], Qh4[kk][2], Qh4[kk][3]);
        ldmx4(b0 + 17408u + qoff, Ql4[kk][0], Ql4[kk][1], Ql4[kk][2], Ql4[kk][3]);
    }

    float m0 = -1e30f, m1 = -1e30f, l0 = 0.f, l1 = 0.f;
    float oa[16][4];
#pragma unroll
    for (int d = 0; d < 16; d++)
#pragma unroll
        for (int r = 0; r < 4; r++) oa[d][r] = 0.f;

    uint32_t kb = b1, vb = b2, fb = b0;
    const int NJT = it + 1;

    for (int jt = 0; jt < NJT; jt++) {
        int j0 = jt * 64;

        // ===== S phase: need K(jt); prefetch K(jt+1) into free buffer =====
        CP_WAIT(1);               // K(jt) done (V(jt) may be pending)
        __syncthreads();          // also: all warps done with PV(jt-1) / Q extraction
        if (jt + 1 < NJT) copyPair(khb, klb, (jt + 1) * 64, fb);

        float s[8][4];
#pragma unroll
        for (int nb = 0; nb < 8; nb++)
#pragma unroll
            for (int r = 0; r < 4; r++) s[nb][r] = 0.f;

#pragma unroll
        for (int kk = 0; kk < 8; kk++) {
#pragma unroll
            for (int np = 0; np < 4; np++) {
                uint32_t koff = ((uint32_t)(np * 16) + lrow) * 272u + lseg16 + (uint32_t)kk * 32u;
                uint32_t h0, h1, h2, h3, l0r, l1r, l2r, l3r;
                ldmx4(kb + koff,          h0, h1, h2, h3);
                ldmx4(kb + 17408u + koff, l0r, l1r, l2r, l3r);
                int nb = np * 2;
                mma16816(s[nb][0], s[nb][1], s[nb][2], s[nb][3],
                         Qh4[kk][0], Qh4[kk][1], Qh4[kk][2], Qh4[kk][3], h0, h2);
                mma16816(s[nb][0], s[nb][1], s[nb][2], s[nb][3],
                         Qh4[kk][0], Qh4[kk][1], Qh4[kk][2], Qh4[kk][3], l0r, l2r);
                mma16816(s[nb][0], s[nb][1], s[nb][2], s[nb][3],
                         Ql4[kk][0], Ql4[kk][1], Ql4[kk][2], Ql4[kk][3], h0, h2);
                mma16816(s[nb + 1][0], s[nb + 1][1], s[nb + 1][2], s[nb + 1][3],
                         Qh4[kk][0], Qh4[kk][1], Qh4[kk][2], Qh4[kk][3], h1, h3);
                mma16816(s[nb + 1][0], s[nb + 1][1], s[nb + 1][2], s[nb + 1][3],
                         Qh4[kk][0], Qh4[kk][1], Qh4[kk][2], Qh4[kk][3], l1r, l3r);
                mma16816(s[nb + 1][0], s[nb + 1][1], s[nb + 1][2], s[nb + 1][3],
                         Ql4[kk][0], Ql4[kk][1], Ql4[kk][2], Ql4[kk][3], h1, h3);
            }
        }

        // ---- causal mask on diagonal tile ----
        if (jt == it) {
            int r0 = warp * 16 + g;
            int r1 = r0 + 8;
#pragma unroll
            for (int nb = 0; nb < 8; nb++) {
                int c0 = nb * 8 + 2 * q4;
                if (c0 > r0)     s[nb][0] = -1e30f;
                if (c0 + 1 > r0) s[nb][1] = -1e30f;
                if (c0 > r1)     s[nb][2] = -1e30f;
                if (c0 + 1 > r1) s[nb][3] = -1e30f;
            }
        }

        // ---- online softmax ----
        float mx0 = -1e30f, mx1 = -1e30f;
#pragma unroll
        for (int nb = 0; nb < 8; nb++) {
            mx0 = fmaxf(mx0, fmaxf(s[nb][0], s[nb][1]));
            mx1 = fmaxf(mx1, fmaxf(s[nb][2], s[nb][3]));
        }
        mx0 = fmaxf(mx0, __shfl_xor_sync(0xffffffffu, mx0, 1));
        mx0 = fmaxf(mx0, __shfl_xor_sync(0xffffffffu, mx0, 2));
        mx1 = fmaxf(mx1, __shfl_xor_sync(0xffffffffu, mx1, 1));
        mx1 = fmaxf(mx1, __shfl_xor_sync(0xffffffffu, mx1, 2));

        float m0n = fmaxf(m0, mx0), m1n = fmaxf(m1, mx1);
        float f0 = __expf(m0 - m0n), f1 = __expf(m1 - m1n);

        float sum0 = 0.f, sum1 = 0.f;
#pragma unroll
        for (int nb = 0; nb < 8; nb++) {
            s[nb][0] = __expf(s[nb][0] - m0n);
            s[nb][1] = __expf(s[nb][1] - m0n);
            s[nb][2] = __expf(s[nb][2] - m1n);
            s[nb][3] = __expf(s[nb][3] - m1n);
            sum0 += s[nb][0] + s[nb][1];
            sum1 += s[nb][2] + s[nb][3];
        }
        sum0 += __shfl_xor_sync(0xffffffffu, sum0, 1);
        sum0 += __shfl_xor_sync(0xffffffffu, sum0, 2);
        sum1 += __shfl_xor_sync(0xffffffffu, sum1, 1);
        sum1 += __shfl_xor_sync(0xffffffffu, sum1, 2);

        m0 = m0n; m1 = m1n;
        l0 = l0 * f0 + sum0;
        l1 = l1 * f1 + sum1;

#pragma unroll
        for (int d = 0; d < 16; d++) {
            oa[d][0] *= f0; oa[d][1] *= f0;
            oa[d][2] *= f1; oa[d][3] *= f1;
        }

        // ---- P -> bf16 hi/lo A-frags ----
        uint32_t Ph[4][4], Pl[4][4];
#pragma unroll
        for (int kk2 = 0; kk2 < 4; kk2++) {
            int nb = 2 * kk2;
#pragma unroll
            for (int half = 0; half < 2; half++) {
                int src = nb + half;
                float p0 = s[src][0], p1 = s[src][1], p2 = s[src][2], p3 = s[src][3];
                __nv_bfloat162 hA = __floats2bfloat162_rn(p0, p1);
                __nv_bfloat162 hB = __floats2bfloat162_rn(p2, p3);
                Ph[kk2][half * 2 + 0] = *(uint32_t*)&hA;
                Ph[kk2][half * 2 + 1] = *(uint32_t*)&hB;
                Pl[kk2][half * 2 + 0] = packbf(p0 - __bfloat162float(__low2bfloat16(hA)),
                                               p1 - __bfloat162float(__high2bfloat16(hA)));
                Pl[kk2][half * 2 + 1] = packbf(p2 - __bfloat162float(__low2bfloat16(hB)),
                                               p3 - __bfloat162float(__high2bfloat16(hB)));
            }
        }

        // ===== PV phase: need V(jt); prefetch V(jt+1) into old K buffer =====
        if (jt + 1 < NJT) { CP_WAIT(1); } else { CP_WAIT(0); }   // V(jt) done
        __syncthreads();          // all warps done reading K(jt)
        uint32_t oldkb = kb;
        if (jt + 1 < NJT) copyPair(vhb, vlb, (jt + 1) * 64, oldkb);

#pragma unroll
        for (int kk2 = 0; kk2 < 4; kk2++) {
#pragma unroll
            for (int dp = 0; dp < 8; dp++) {
                uint32_t voff = ((uint32_t)(kk2 * 16) + lrow) * 272u
                              + (uint32_t)dp * 32u + lseg16;
                uint32_t h0, h1, h2, h3, l0r, l1r, l2r, l3r;
                ldmx4t(vb + voff,          h0, h1, h2, h3);
                ldmx4t(vb + 17408u + voff, l0r, l1r, l2r, l3r);
                int dnb = dp * 2;
                mma16816(oa[dnb][0], oa[dnb][1], oa[dnb][2], oa[dnb][3],
                         Ph[kk2][0], Ph[kk2][1], Ph[kk2][2], Ph[kk2][3], h0, h1);
                mma16816(oa[dnb][0], oa[dnb][1], oa[dnb][2], oa[dnb][3],
                         Ph[kk2][0], Ph[kk2][1], Ph[kk2][2], Ph[kk2][3], l0r, l1r);
                mma16816(oa[dnb][0], oa[dnb][1], oa[dnb][2], oa[dnb][3],
                         Pl[kk2][0], Pl[kk2][1], Pl[kk2][2], Pl[kk2][3], h0, h1);
                mma16816(oa[dnb + 1][0], oa[dnb + 1][1], oa[dnb + 1][2], oa[dnb + 1][3],
                         Ph[kk2][0], Ph[kk2][1], Ph[kk2][2], Ph[kk2][3], h2, h3);
                mma16816(oa[dnb + 1][0], oa[dnb + 1][1], oa[dnb + 1][2], oa[dnb + 1][3],
                         Ph[kk2][0], Ph[kk2][1], Ph[kk2][2], Ph[kk2][3], l2r, l3r);
                mma16816(oa[dnb + 1][0], oa[dnb + 1][1], oa[dnb + 1][2], oa[dnb + 1][3],
                         Pl[kk2][0], Pl[kk2][1], Pl[kk2][2], Pl[kk2][3], h2, h3);
            }
        }

        // rotate buffers: K(jt+1) is in fb, V(jt+1) is in oldkb, free = old vb
        uint32_t newk = fb;
        fb = vb;
        vb = oldkb;
        kb = newk;
    }

    // ---- epilogue: normalize, split to bf16 hi/lo ----
    float inv0 = 1.0f / l0, inv1 = 1.0f / l1;
    int r0 = i0 + warp * 16 + g;
    __nv_bfloat16* ohb = oh + hoff;
    __nv_bfloat16* olb = ol + hoff;
#pragma unroll
    for (int dnb = 0; dnb < 16; dnb++) {
        int col = dnb * 8 + 2 * q4;
        float a0 = oa[dnb][0] * inv0, a1 = oa[dnb][1] * inv0;
        float b0f = oa[dnb][2] * inv1, b1f = oa[dnb][3] * inv1;
        __nv_bfloat162 h0 = __floats2bfloat162_rn(a0, a1);
        __nv_bfloat162 h1 = __floats2bfloat162_rn(b0f, b1f);
        *(__nv_bfloat162*)&ohb[(size_t)r0 * DMODEL + col] = h0;
        *(__nv_bfloat162*)&ohb[(size_t)(r0 + 8) * DMODEL + col] = h1;
        __nv_bfloat162 lo0, lo1;
        lo0 = __floats2bfloat162_rn(a0 - __bfloat162float(__low2bfloat16(h0)),
                                    a1 - __bfloat162float(__high2bfloat16(h0)));
        lo1 = __floats2bfloat162_rn(b0f - __bfloat162float(__low2bfloat16(h1)),
                                    b1f - __bfloat162float(__high2bfloat16(h1)));
        *(__nv_bfloat162*)&olb[(size_t)r0 * DMODEL + col] = lo0;
        *(__nv_bfloat162*)&olb[(size_t)(r0 + 8) * DMODEL + col] = lo1;
    }
}

// ---------------------------------------------------------------------------
extern "C" void kernel_launch(void* const* d_in, const int* in_sizes, int n_in,
                              void* d_out, int out_size)
{
    const float* x  = (const float*)d_in[0];
    const float* Wq = (const float*)d_in[1];
    const float* bq = (const float*)d_in[2];
    const float* Wk = (const float*)d_in[3];
    const float* bk = (const float*)d_in[4];
    const float* Wv = (const float*)d_in[5];
    const float* bv = (const float*)d_in[6];
    const float* Wo = (const float*)d_in[7];
    const float* bo = (const float*)d_in[8];
    float* out = (float*)d_out;

    __nv_bfloat16 *xhi, *xlo, *ahi, *alo, *qhh, *qll, *khh, *kll, *vhh, *vll;
    __nv_bfloat16 *wqh, *wql, *wkh, *wkl, *wvh, *wvl, *woh, *wol;
    cudaGetSymbolAddress((void**)&xhi, g_xhi);
    cudaGetSymbolAddress((void**)&xlo, g_xlo);
    cudaGetSymbolAddress((void**)&ahi, g_ahi);
    cudaGetSymbolAddress((void**)&alo, g_alo);
    cudaGetSymbolAddress((void**)&qhh, g_qh);
    cudaGetSymbolAddress((void**)&qll, g_ql);
    cudaGetSymbolAddress((void**)&khh, g_kh);
    cudaGetSymbolAddress((void**)&kll, g_kl);
    cudaGetSymbolAddress((void**)&vhh, g_vh);
    cudaGetSymbolAddress((void**)&vll, g_vl);
    cudaGetSymbolAddress((void**)&wqh, g_wq_hi);
    cudaGetSymbolAddress((void**)&wql, g_wq_lo);
    cudaGetSymbolAddress((void**)&wkh, g_wk_hi);
    cudaGetSymbolAddress((void**)&wkl, g_wk_lo);
    cudaGetSymbolAddress((void**)&wvh, g_wv_hi);
    cudaGetSymbolAddress((void**)&wvl, g_wv_lo);
    cudaGetSymbolAddress((void**)&woh, g_wo_hi);
    cudaGetSymbolAddress((void**)&wol, g_wo_lo);

    cudaFuncSetAttribute(gemm_qkv, cudaFuncAttributeMaxDynamicSharedMemorySize, GEMM_SMEM);
    cudaFuncSetAttribute(gemm_bf16x2, cudaFuncAttributeMaxDynamicSharedMemorySize, GEMM_SMEM);
    cudaFuncSetAttribute(flash_attn_mma, cudaFuncAttributeMaxDynamicSharedMemorySize, ATT_SMEM);

    // prep: split x, transpose+split all 4 weights in one launch
    int n4x = ROWS * DMODEL / 4;
    split_kernel<<<(n4x + 255) / 256, 256>>>((const float4*)x, xhi, xlo, n4x);
    dim3 tgrid(DMODEL / 32, DMODEL / 32, 4);
    transpose_split4<<<tgrid, 256>>>(Wq, Wk, Wv, Wo,
                                     wqh, wql, wkh, wkl, wvh, wvl, woh, wol);

    // fused QKV projection + rotary + split
    dim3 qkv_grid(3 * DMODEL / TN, ROWS / TM);   // (48, 32)
    gemm_qkv<<<qkv_grid, 256, GEMM_SMEM>>>(xhi, xlo, wqh, wql, wkh, wkl, wvh, wvl,
                                           bq, bk, bv, qhh, qll, khh, kll, vhh, vll);

    // tensor-core flash attention (emits bf16 hi/lo)
    dim3 attn_grid(NSEQ / 64, BATCH * HEADS);   // (32, 32)
    flash_attn_mma<<<attn_grid, 128, ATT_SMEM>>>(qhh, qll, khh, kll, vhh, vll, ahi, alo);

    // output projection
    dim3 ggrid(DMODEL / TN, ROWS / TM);   // (16, 32)
    gemm_bf16x2<<<ggrid, 256, GEMM_SMEM>>>(ahi, alo, woh, wol, bo, out);
}

// round 8
// speedup vs baseline: 1.5796x; 1.5335x over previous
#include <cuda_runtime.h>
#include <cuda_fp16.h>
#include <math.h>
#include <stdint.h>

#define BATCH 2
#define NSEQ  2048
#define DMODEL 2048
#define HEADS 16
#define DHEAD 128
#define ROWS (BATCH*NSEQ)   // 4096

// ---------------------------------------------------------------------------
// scratch (device globals: no allocation allowed)
// ---------------------------------------------------------------------------
__device__ __half g_xhi[ROWS*DMODEL];
__device__ __half g_xlo[ROWS*DMODEL];
__device__ __half g_ahi[ROWS*DMODEL];
__device__ __half g_alo[ROWS*DMODEL];
__device__ __half g_qh[ROWS*DMODEL];
__device__ __half g_ql[ROWS*DMODEL];
__device__ __half g_kh[ROWS*DMODEL];
__device__ __half g_vh[ROWS*DMODEL];
__device__ __half g_wq[DMODEL*DMODEL];
__device__ __half g_wk[DMODEL*DMODEL];
__device__ __half g_wv[DMODEL*DMODEL];
__device__ __half g_wo[DMODEL*DMODEL];

// ---------------------------------------------------------------------------
// helpers
// ---------------------------------------------------------------------------
__device__ __forceinline__ uint32_t smem_u32(const void* p) {
    uint32_t a;
    asm("{ .reg .u64 t; cvta.to.shared.u64 t, %1; cvt.u32.u64 %0, t; }" : "=r"(a) : "l"(p));
    return a;
}

__device__ __forceinline__ void cp16(uint32_t dst, const void* src) {
    asm volatile("cp.async.cg.shared.global [%0], [%1], 16;" :: "r"(dst), "l"(src));
}
#define CP_COMMIT() asm volatile("cp.async.commit_group;" ::: "memory")
#define CP_WAIT(n)  asm volatile("cp.async.wait_group %0;" :: "n"(n) : "memory")

__device__ __forceinline__ void ldmx4(uint32_t addr, uint32_t& r0, uint32_t& r1,
                                      uint32_t& r2, uint32_t& r3) {
    asm volatile("ldmatrix.sync.aligned.m8n8.x4.shared.b16 {%0,%1,%2,%3}, [%4];"
                 : "=r"(r0), "=r"(r1), "=r"(r2), "=r"(r3) : "r"(addr));
}
__device__ __forceinline__ void ldmx4t(uint32_t addr, uint32_t& r0, uint32_t& r1,
                                       uint32_t& r2, uint32_t& r3) {
    asm volatile("ldmatrix.sync.aligned.m8n8.x4.trans.shared.b16 {%0,%1,%2,%3}, [%4];"
                 : "=r"(r0), "=r"(r1), "=r"(r2), "=r"(r3) : "r"(addr));
}

// fp16 inputs, fp32 accumulate
__device__ __forceinline__ void mma16816(float& c0, float& c1, float& c2, float& c3,
                                         uint32_t a0, uint32_t a1, uint32_t a2, uint32_t a3,
                                         uint32_t b0, uint32_t b1) {
    asm volatile(
        "mma.sync.aligned.m16n8k16.row.col.f32.f16.f16.f32 "
        "{%0,%1,%2,%3}, {%4,%5,%6,%7}, {%8,%9}, {%0,%1,%2,%3};"
        : "+f"(c0), "+f"(c1), "+f"(c2), "+f"(c3)
        : "r"(a0), "r"(a1), "r"(a2), "r"(a3), "r"(b0), "r"(b1));
}

__device__ __forceinline__ uint32_t packh(float a, float b) {
    __half2 t = __floats2half2_rn(a, b);
    return *(uint32_t*)&t;
}

// ---------------------------------------------------------------------------
// split: fp32 -> (hi, lo) fp16 pair
// ---------------------------------------------------------------------------
__global__ __launch_bounds__(256)
void split_kernel(const float4* __restrict__ in, __half* __restrict__ hi,
                  __half* __restrict__ lo, int n4)
{
    int i = blockIdx.x * 256 + threadIdx.x;
    if (i >= n4) return;
    float4 v = in[i];
    __half h0 = __float2half(v.x);
    __half h1 = __float2half(v.y);
    __half h2 = __float2half(v.z);
    __half h3 = __float2half(v.w);
    __half2* hp = (__half2*)(hi + 4 * (size_t)i);
    hp[0] = __half2(h0, h1);
    hp[1] = __half2(h2, h3);
    __half2* lp = (__half2*)(lo + 4 * (size_t)i);
    lp[0] = __half2(__float2half(v.x - __half2float(h0)),
                    __float2half(v.y - __half2float(h1)));
    lp[1] = __half2(__float2half(v.z - __half2float(h2)),
                    __float2half(v.w - __half2float(h3)));
}

// ---------------------------------------------------------------------------
// transpose + convert: W[K][N] fp32 -> Wt[N][K] fp16 (hi only), 4 weights
// ---------------------------------------------------------------------------
__global__ __launch_bounds__(256)
void transpose_cvt4(const float* __restrict__ W0, const float* __restrict__ W1,
                    const float* __restrict__ W2, const float* __restrict__ W3,
                    __half* __restrict__ t0, __half* __restrict__ t1,
                    __half* __restrict__ t2, __half* __restrict__ t3)
{
    int z = blockIdx.z;
    const float* W = (z == 0) ? W0 : (z == 1) ? W1 : (z == 2) ? W2 : W3;
    __half* th = (z == 0) ? t0 : (z == 1) ? t1 : (z == 2) ? t2 : t3;

    __shared__ float t[32][33];
    int n0 = blockIdx.x * 32, k0 = blockIdx.y * 32;
    int tx = threadIdx.x & 31, ty = threadIdx.x >> 5;
#pragma unroll
    for (int i = 0; i < 32; i += 8)
        t[ty + i][tx] = W[(size_t)(k0 + ty + i) * DMODEL + n0 + tx];
    __syncthreads();
#pragma unroll
    for (int i = 0; i < 32; i += 8)
        th[(size_t)(n0 + ty + i) * DMODEL + k0 + tx] = __float2half(t[tx][ty + i]);
}

// ---------------------------------------------------------------------------
// GEMM config: 2-pass fp16 split, C = (Ah+Al) @ Bh^T + bias
// CTA 128x128, KC=64, double-buffered, 3 tiles/stage (Ah, Al, Bh)
// ---------------------------------------------------------------------------
#define GK DMODEL
#define TM 128
#define TN 128
#define KC 64
#define RSTRB 144u                    // bytes per smem row (128 data + 16 pad)
#define TILE_B (128u * RSTRB)         // 18432
#define STAGE_B (3u * TILE_B)         // 55296
#define GEMM_SMEM (2u * STAGE_B)      // 110592

#define GEMM_MAINLOOP(ACC)                                                              \
    const int NCH = GK / KC;                                                            \
    copy_chunk(0, 0);                                                                   \
    const uint32_t lrow = (uint32_t)(lane & 15);                                        \
    const uint32_t lcol2 = (uint32_t)((lane >> 4) & 1) * 16u;                           \
    for (int c = 0; c < NCH; c++) {                                                     \
        int stg = c & 1;                                                                \
        if (c + 1 < NCH) {                                                              \
            copy_chunk(c + 1, stg ^ 1);                                                 \
            CP_WAIT(1);                                                                 \
        } else {                                                                        \
            CP_WAIT(0);                                                                 \
        }                                                                               \
        __syncthreads();                                                                \
        uint32_t base = sb + (uint32_t)stg * STAGE_B;                                   \
        uint32_t ah_b = base;                                                           \
        uint32_t al_b = base + TILE_B;                                                  \
        uint32_t bh_b = base + 2u * TILE_B;                                             \
        _Pragma("unroll")                                                               \
        for (int kk = 0; kk < 4; kk++) {                                                \
            uint32_t koff = (uint32_t)kk * 32u + lcol2;                                 \
            uint32_t Ah[4][4], Al[4][4];                                                \
            _Pragma("unroll")                                                           \
            for (int mi = 0; mi < 4; mi++) {                                            \
                uint32_t roff = ((uint32_t)(wm * 64 + mi * 16) + lrow) * RSTRB + koff;  \
                ldmx4(ah_b + roff, Ah[mi][0], Ah[mi][1], Ah[mi][2], Ah[mi][3]);         \
                ldmx4(al_b + roff, Al[mi][0], Al[mi][1], Al[mi][2], Al[mi][3]);         \
            }                                                                           \
            uint32_t Bh[4][2];                                                          \
            _Pragma("unroll")                                                           \
            for (int np = 0; np < 2; np++) {                                            \
                uint32_t roff = ((uint32_t)(wn * 32 + np * 16) + lrow) * RSTRB + koff;  \
                uint32_t r0, r1, r2, r3;                                                \
                ldmx4(bh_b + roff, r0, r1, r2, r3);                                     \
                Bh[np * 2][0] = r0; Bh[np * 2 + 1][0] = r1;                             \
                Bh[np * 2][1] = r2; Bh[np * 2 + 1][1] = r3;                             \
            }                                                                           \
            _Pragma("unroll")                                                           \
            for (int mi = 0; mi < 4; mi++)                                              \
                _Pragma("unroll")                                                       \
                for (int ni = 0; ni < 4; ni++) {                                        \
                    mma16816(ACC[mi][ni][0], ACC[mi][ni][1], ACC[mi][ni][2], ACC[mi][ni][3], \
                             Ah[mi][0], Ah[mi][1], Ah[mi][2], Ah[mi][3],                \
                             Bh[ni][0], Bh[ni][1]);                                     \
                    mma16816(ACC[mi][ni][0], ACC[mi][ni][1], ACC[mi][ni][2], ACC[mi][ni][3], \
                             Al[mi][0], Al[mi][1], Al[mi][2], Al[mi][3],                \
                             Bh[ni][0], Bh[ni][1]);                                     \
                }                                                                       \
        }                                                                               \
        __syncthreads();                                                                \
    }

#define GEMM_COPY_CHUNK                                                                 \
    auto copy_chunk = [&](int c, int stg) {                                             \
        int k0 = c * KC;                                                                \
        uint32_t base = sb + (uint32_t)stg * STAGE_B;                                   \
        const __half* srcs[3] = { Ahi, Alo, Bhh };                                      \
        int rows0[3] = { brow, brow, bcol };                                            \
        _Pragma("unroll")                                                               \
        for (int t = 0; t < 3; t++) {                                                   \
            const __half* src = srcs[t] + (size_t)rows0[t] * GK + k0;                   \
            uint32_t tb = base + (uint32_t)t * TILE_B;                                  \
            _Pragma("unroll")                                                           \
            for (int i = 0; i < 4; i++) {                                               \
                int s = i * 256 + tid;                                                  \
                int r = s >> 3, seg = s & 7;                                            \
                cp16(tb + (uint32_t)r * RSTRB + (uint32_t)seg * 16u,                    \
                     src + (size_t)r * GK + seg * 8);                                   \
            }                                                                           \
        }                                                                               \
        CP_COMMIT();                                                                    \
    };

// ---------------------------------------------------------------------------
// Fused QKV GEMM + rotary + fp16 split epilogue. grid (48, 32).
// q -> hi+lo; k,v -> hi only.
// ---------------------------------------------------------------------------
__global__ __launch_bounds__(256, 2)
void gemm_qkv(const __half* __restrict__ xhi, const __half* __restrict__ xlo,
              const __half* __restrict__ wq, const __half* __restrict__ wk,
              const __half* __restrict__ wv,
              const float* __restrict__ bq, const float* __restrict__ bk,
              const float* __restrict__ bv,
              __half* __restrict__ qh, __half* __restrict__ ql,
              __half* __restrict__ kh, __half* __restrict__ vh)
{
    extern __shared__ __align__(128) char smem[];
    uint32_t sb = smem_u32(smem);
    const int tid  = threadIdx.x;
    const int wid  = tid >> 5;
    const int lane = tid & 31;
    const int brow = blockIdx.y * TM;
    const int mtx  = blockIdx.x >> 4;            // 0=q, 1=k, 2=v
    const int bcol = (blockIdx.x & 15) * TN;

    const __half* Ahi = xhi;
    const __half* Alo = xlo;
    const __half* Bhh = (mtx == 0) ? wq : (mtx == 1) ? wk : wv;
    const float* bias = (mtx == 0) ? bq : (mtx == 1) ? bk : bv;

    const int wm = wid & 1;
    const int wn = wid >> 1;

    float acc[4][4][4];
#pragma unroll
    for (int i = 0; i < 4; i++)
#pragma unroll
        for (int j = 0; j < 4; j++)
#pragma unroll
            for (int r = 0; r < 4; r++) acc[i][j][r] = 0.f;

    GEMM_COPY_CHUNK
    GEMM_MAINLOOP(acc)

    // ------ fused epilogue: stage fp32 tile in smem, rotary+split, store ----
    float* ft = (float*)smem;    // [128][132] fp32 = 67584 B
    int g = lane >> 2, t4 = lane & 3;
#pragma unroll
    for (int mi = 0; mi < 4; mi++) {
        int r0 = wm * 64 + mi * 16 + g;
#pragma unroll
        for (int ni = 0; ni < 4; ni++) {
            int cl = wn * 32 + ni * 8 + 2 * t4;
            float2 b01 = *(const float2*)&bias[bcol + cl];
            *(float2*)&ft[r0 * 132 + cl] =
                make_float2(acc[mi][ni][0] + b01.x, acc[mi][ni][1] + b01.y);
            *(float2*)&ft[(r0 + 8) * 132 + cl] =
                make_float2(acc[mi][ni][2] + b01.x, acc[mi][ni][3] + b01.y);
        }
    }
    __syncthreads();

    const bool  do_rot = (mtx < 2);
    const float scale  = (mtx == 0) ? 0.08838834764831845f : 1.0f;
    int d  = tid & 63;
    int rb = tid >> 6;
    float inv_freq = __expf(-(float)d * (9.210340371976184f / 64.0f));

    for (int rr = rb; rr < 128; rr += 4) {
        int grow = brow + rr;
        float a = ft[rr * 132 + d];
        float b2 = ft[rr * 132 + d + 64];
        float oa, ob2;
        if (do_rot) {
            int n = grow & (NSEQ - 1);
            float s, c;
            sincosf((float)n * inv_freq, &s, &c);
            oa  = (a * c - b2 * s) * scale;
            ob2 = (b2 * c + a * s) * scale;
        } else {
            oa = a; ob2 = b2;
        }
        size_t base = (size_t)grow * DMODEL + bcol + d;
        if (mtx == 0) {
            __half h = __float2half(oa);
            qh[base] = h;
            ql[base] = __float2half(oa - __half2float(h));
            h = __float2half(ob2);
            qh[base + 64] = h;
            ql[base + 64] = __float2half(ob2 - __half2float(h));
        } else {
            __half* Oh = (mtx == 1) ? kh : vh;
            Oh[base]      = __float2half(oa);
            Oh[base + 64] = __float2half(ob2);
        }
    }
}

// ---------------------------------------------------------------------------
// GEMM 2-pass, fp32 output + bias — out projection
// ---------------------------------------------------------------------------
__global__ __launch_bounds__(256, 2)
void gemm_2p(const __half* __restrict__ Ahi, const __half* __restrict__ Alo,
             const __half* __restrict__ Bhh,
             const float* __restrict__ bias, float* __restrict__ C)
{
    extern __shared__ __align__(128) char smem[];
    uint32_t sb = smem_u32(smem);
    const int tid  = threadIdx.x;
    const int wid  = tid >> 5;
    const int lane = tid & 31;
    const int brow = blockIdx.y * TM;
    const int bcol = blockIdx.x * TN;

    const int wm = wid & 1;
    const int wn = wid >> 1;

    float acc[4][4][4];
#pragma unroll
    for (int i = 0; i < 4; i++)
#pragma unroll
        for (int j = 0; j < 4; j++)
#pragma unroll
            for (int r = 0; r < 4; r++) acc[i][j][r] = 0.f;

    GEMM_COPY_CHUNK
    GEMM_MAINLOOP(acc)

    int g = lane >> 2, t4 = lane & 3;
#pragma unroll
    for (int mi = 0; mi < 4; mi++) {
        int r0 = brow + wm * 64 + mi * 16 + g;
#pragma unroll
        for (int ni = 0; ni < 4; ni++) {
            int col = bcol + wn * 32 + ni * 8 + 2 * t4;
            float2 b01 = *(const float2*)&bias[col];
            float2 o0, o1;
            o0.x = acc[mi][ni][0] + b01.x;
            o0.y = acc[mi][ni][1] + b01.y;
            o1.x = acc[mi][ni][2] + b01.x;
            o1.y = acc[mi][ni][3] + b01.y;
            *(float2*)&C[(size_t)r0 * DMODEL + col]       = o0;
            *(float2*)&C[(size_t)(r0 + 8) * DMODEL + col] = o1;
        }
    }
}

// ---------------------------------------------------------------------------
// Flash attention (causal), fp16 2-pass: S=(Qh+Ql)Kh, O=(Ph+Pl)Vh.
// BR=BC=64, 128 threads, Q in regs, 3 rotating 17KB K/V buffers.
// ---------------------------------------------------------------------------
#define ABUF_B 17408u
#define ATT_SMEM (3u * ABUF_B)        // 52224

__global__ __launch_bounds__(128)
void flash_attn_mma(const __half* __restrict__ qh, const __half* __restrict__ ql,
                    const __half* __restrict__ kh, const __half* __restrict__ vh,
                    __half* __restrict__ oh, __half* __restrict__ ol)
{
    extern __shared__ __align__(128) char smem[];
    uint32_t sb = smem_u32(smem);

    const int tid  = threadIdx.x;
    const int warp = tid >> 5;
    const int lane = tid & 31;
    const int g    = lane >> 2;
    const int q4   = lane & 3;

    const int it = gridDim.x - 1 - blockIdx.x;   // heavy tiles first
    const int bh = blockIdx.y;
    const int b = bh >> 4, h = bh & 15;
    const int i0 = it * 64;

    const size_t hoff = (size_t)b * NSEQ * DMODEL + h * DHEAD;
    const __half* qhb = qh + hoff;
    const __half* qlb = ql + hoff;
    const __half* khb = kh + hoff;
    const __half* vhb = vh + hoff;

    // copy one 64-row fp16 tile (256B rows at 272B stride), one commit group
    auto copyTile = [&](const __half* src, int row0, uint32_t buf) {
#pragma unroll
        for (int i = 0; i < 8; i++) {
            int s = i * 128 + tid;
            int r = s >> 4, seg = s & 15;
            cp16(buf + (uint32_t)r * 272u + (uint32_t)seg * 16u,
                 src + (size_t)(row0 + r) * DMODEL + seg * 8);
        }
        CP_COMMIT();
    };

    uint32_t b0 = sb, b1 = sb + ABUF_B, b2 = sb + 2u * ABUF_B;

    copyTile(qhb, i0, b0);   // g1
    copyTile(qlb, i0, b1);   // g2
    copyTile(khb, 0,  b2);   // g3: K(0)

    CP_WAIT(1);              // Qh, Ql done
    __syncthreads();

    // hoist Q fragments into registers
    const uint32_t lrow = (uint32_t)(lane & 15);
    const uint32_t lseg16 = (uint32_t)(lane >> 4) * 16u;
    uint32_t Qh4[8][4], Ql4[8][4];
#pragma unroll
    for (int kk = 0; kk < 8; kk++) {
        uint32_t qoff = ((uint32_t)(warp * 16) + lrow) * 272u + lseg16 + (uint32_t)kk * 32u;
        ldmx4(b0 + qoff, Qh4[kk][0], Qh4[kk][1], Qh4[kk][2], Qh4[kk][3]);
        ldmx4(b1 + qoff, Ql4[kk][0], Ql4[kk][1], Ql4[kk][2], Ql4[kk][3]);
    }
    __syncthreads();
    copyTile(vhb, 0, b0);    // g4: V(0) into Qh's old buffer

    float m0 = -1e30f, m1 = -1e30f, l0 = 0.f, l1 = 0.f;
    float oa[16][4];
#pragma unroll
    for (int d = 0; d < 16; d++)
#pragma unroll
        for (int r = 0; r < 4; r++) oa[d][r] = 0.f;

    uint32_t kb = b2, vb = b0, fb = b1;
    const int NJT = it + 1;

    for (int jt = 0; jt < NJT; jt++) {
        // ===== S phase =====
        CP_WAIT(1);           // K(jt) done (V(jt) may be pending)
        __syncthreads();
        if (jt + 1 < NJT) copyTile(khb, (jt + 1) * 64, fb);

        float s[8][4];
#pragma unroll
        for (int nb = 0; nb < 8; nb++)
#pragma unroll
            for (int r = 0; r < 4; r++) s[nb][r] = 0.f;

#pragma unroll
        for (int kk = 0; kk < 8; kk++) {
#pragma unroll
            for (int np = 0; np < 4; np++) {
                uint32_t koff = ((uint32_t)(np * 16) + lrow) * 272u + lseg16 + (uint32_t)kk * 32u;
                uint32_t h0, h1, h2, h3;
                ldmx4(kb + koff, h0, h1, h2, h3);
                int nb = np * 2;
                mma16816(s[nb][0], s[nb][1], s[nb][2], s[nb][3],
                         Qh4[kk][0], Qh4[kk][1], Qh4[kk][2], Qh4[kk][3], h0, h2);
                mma16816(s[nb][0], s[nb][1], s[nb][2], s[nb][3],
                         Ql4[kk][0], Ql4[kk][1], Ql4[kk][2], Ql4[kk][3], h0, h2);
                mma16816(s[nb + 1][0], s[nb + 1][1], s[nb + 1][2], s[nb + 1][3],
                         Qh4[kk][0], Qh4[kk][1], Qh4[kk][2], Qh4[kk][3], h1, h3);
                mma16816(s[nb + 1][0], s[nb + 1][1], s[nb + 1][2], s[nb + 1][3],
                         Ql4[kk][0], Ql4[kk][1], Ql4[kk][2], Ql4[kk][3], h1, h3);
            }
        }

        // causal mask on diagonal tile
        if (jt == it) {
            int r0 = warp * 16 + g;
            int r1 = r0 + 8;
#pragma unroll
            for (int nb = 0; nb < 8; nb++) {
                int c0 = nb * 8 + 2 * q4;
                if (c0 > r0)     s[nb][0] = -1e30f;
                if (c0 + 1 > r0) s[nb][1] = -1e30f;
                if (c0 > r1)     s[nb][2] = -1e30f;
                if (c0 + 1 > r1) s[nb][3] = -1e30f;
            }
        }

        // online softmax
        float mx0 = -1e30f, mx1 = -1e30f;
#pragma unroll
        for (int nb = 0; nb < 8; nb++) {
            mx0 = fmaxf(mx0, fmaxf(s[nb][0], s[nb][1]));
            mx1 = fmaxf(mx1, fmaxf(s[nb][2], s[nb][3]));
        }
        mx0 = fmaxf(mx0, __shfl_xor_sync(0xffffffffu, mx0, 1));
        mx0 = fmaxf(mx0, __shfl_xor_sync(0xffffffffu, mx0, 2));
        mx1 = fmaxf(mx1, __shfl_xor_sync(0xffffffffu, mx1, 1));
        mx1 = fmaxf(mx1, __shfl_xor_sync(0xffffffffu, mx1, 2));

        float m0n = fmaxf(m0, mx0), m1n = fmaxf(m1, mx1);
        float f0 = __expf(m0 - m0n), f1 = __expf(m1 - m1n);

        float sum0 = 0.f, sum1 = 0.f;
#pragma unroll
        for (int nb = 0; nb < 8; nb++) {
            s[nb][0] = __expf(s[nb][0] - m0n);
            s[nb][1] = __expf(s[nb][1] - m0n);
            s[nb][2] = __expf(s[nb][2] - m1n);
            s[nb][3] = __expf(s[nb][3] - m1n);
            sum0 += s[nb][0] + s[nb][1];
            sum1 += s[nb][2] + s[nb][3];
        }
        sum0 += __shfl_xor_sync(0xffffffffu, sum0, 1);
        sum0 += __shfl_xor_sync(0xffffffffu, sum0, 2);
        sum1 += __shfl_xor_sync(0xffffffffu, sum1, 1);
        sum1 += __shfl_xor_sync(0xffffffffu, sum1, 2);

        m0 = m0n; m1 = m1n;
        l0 = l0 * f0 + sum0;
        l1 = l1 * f1 + sum1;

#pragma unroll
        for (int d = 0; d < 16; d++) {
            oa[d][0] *= f0; oa[d][1] *= f0;
            oa[d][2] *= f1; oa[d][3] *= f1;
        }

        // P -> fp16 hi/lo A-frags
        uint32_t Ph[4][4], Pl[4][4];
#pragma unroll
        for (int kk2 = 0; kk2 < 4; kk2++) {
            int nb = 2 * kk2;
#pragma unroll
            for (int half = 0; half < 2; half++) {
                int src = nb + half;
                float p0 = s[src][0], p1 = s[src][1], p2 = s[src][2], p3 = s[src][3];
                __half2 hA = __floats2half2_rn(p0, p1);
                __half2 hB = __floats2half2_rn(p2, p3);
                Ph[kk2][half * 2 + 0] = *(uint32_t*)&hA;
                Ph[kk2][half * 2 + 1] = *(uint32_t*)&hB;
                Pl[kk2][half * 2 + 0] = packh(p0 - __half2float(__low2half(hA)),
                                              p1 - __half2float(__high2half(hA)));
                Pl[kk2][half * 2 + 1] = packh(p2 - __half2float(__low2half(hB)),
                                              p3 - __half2float(__high2half(hB)));
            }
        }

        // ===== PV phase =====
        if (jt + 1 < NJT) { CP_WAIT(1); } else { CP_WAIT(0); }   // V(jt) done
        __syncthreads();
        uint32_t oldkb = kb;
        if (jt + 1 < NJT) copyTile(vhb, (jt + 1) * 64, oldkb);

#pragma unroll
        for (int kk2 = 0; kk2 < 4; kk2++) {
#pragma unroll
            for (int dp = 0; dp < 8; dp++) {
                uint32_t voff = ((uint32_t)(kk2 * 16) + lrow) * 272u
                              + (uint32_t)dp * 32u + lseg16;
                uint32_t h0, h1, h2, h3;
                ldmx4t(vb + voff, h0, h1, h2, h3);
                int dnb = dp * 2;
                mma16816(oa[dnb][0], oa[dnb][1], oa[dnb][2], oa[dnb][3],
                         Ph[kk2][0], Ph[kk2][1], Ph[kk2][2], Ph[kk2][3], h0, h1);
                mma16816(oa[dnb][0], oa[dnb][1], oa[dnb][2], oa[dnb][3],
                         Pl[kk2][0], Pl[kk2][1], Pl[kk2][2], Pl[kk2][3], h0, h1);
                mma16816(oa[dnb + 1][0], oa[dnb + 1][1], oa[dnb + 1][2], oa[dnb + 1][3],
                         Ph[kk2][0], Ph[kk2][1], Ph[kk2][2], Ph[kk2][3], h2, h3);
                mma16816(oa[dnb + 1][0], oa[dnb + 1][1], oa[dnb + 1][2], oa[dnb + 1][3],
                         Pl[kk2][0], Pl[kk2][1], Pl[kk2][2], Pl[kk2][3], h2, h3);
            }
        }

        // rotate: K(jt+1) in fb, V(jt+1) in oldkb, free = old vb
        uint32_t newk = fb;
        fb = vb;
        vb = oldkb;
        kb = newk;
    }

    // epilogue: normalize, split to fp16 hi/lo
    float inv0 = 1.0f / l0, inv1 = 1.0f / l1;
    int r0 = i0 + warp * 16 + g;
    __half* ohb = oh + hoff;
    __half* olb = ol + hoff;
#pragma unroll
    for (int dnb = 0; dnb < 16; dnb++) {
        int col = dnb * 8 + 2 * q4;
        float a0 = oa[dnb][0] * inv0, a1 = oa[dnb][1] * inv0;
        float b0f = oa[dnb][2] * inv1, b1f = oa[dnb][3] * inv1;
        __half2 h0 = __floats2half2_rn(a0, a1);
        __half2 h1 = __floats2half2_rn(b0f, b1f);
        *(__half2*)&ohb[(size_t)r0 * DMODEL + col] = h0;
        *(__half2*)&ohb[(size_t)(r0 + 8) * DMODEL + col] = h1;
        __half2 lo0 = __floats2half2_rn(a0 - __half2float(__low2half(h0)),
                                        a1 - __half2float(__high2half(h0)));
        __half2 lo1 = __floats2half2_rn(b0f - __half2float(__low2half(h1)),
                                        b1f - __half2float(__high2half(h1)));
        *(__half2*)&olb[(size_t)r0 * DMODEL + col] = lo0;
        *(__half2*)&olb[(size_t)(r0 + 8) * DMODEL + col] = lo1;
    }
}

// ---------------------------------------------------------------------------
extern "C" void kernel_launch(void* const* d_in, const int* in_sizes, int n_in,
                              void* d_out, int out_size)
{
    const float* x  = (const float*)d_in[0];
    const float* Wq = (const float*)d_in[1];
    const float* bq = (const float*)d_in[2];
    const float* Wk = (const float*)d_in[3];
    const float* bk = (const float*)d_in[4];
    const float* Wv = (const float*)d_in[5];
    const float* bv = (const float*)d_in[6];
    const float* Wo = (const float*)d_in[7];
    const float* bo = (const float*)d_in[8];
    float* out = (float*)d_out;

    __half *xhi, *xlo, *ahi, *alo, *qhh, *qll, *khh, *vhh;
    __half *wq, *wk, *wv, *wo;
    cudaGetSymbolAddress((void**)&xhi, g_xhi);
    cudaGetSymbolAddress((void**)&xlo, g_xlo);
    cudaGetSymbolAddress((void**)&ahi, g_ahi);
    cudaGetSymbolAddress((void**)&alo, g_alo);
    cudaGetSymbolAddress((void**)&qhh, g_qh);
    cudaGetSymbolAddress((void**)&qll, g_ql);
    cudaGetSymbolAddress((void**)&khh, g_kh);
    cudaGetSymbolAddress((void**)&vhh, g_vh);
    cudaGetSymbolAddress((void**)&wq, g_wq);
    cudaGetSymbolAddress((void**)&wk, g_wk);
    cudaGetSymbolAddress((void**)&wv, g_wv);
    cudaGetSymbolAddress((void**)&wo, g_wo);

    cudaFuncSetAttribute(gemm_qkv, cudaFuncAttributeMaxDynamicSharedMemorySize, GEMM_SMEM);
    cudaFuncSetAttribute(gemm_2p, cudaFuncAttributeMaxDynamicSharedMemorySize, GEMM_SMEM);
    cudaFuncSetAttribute(flash_attn_mma, cudaFuncAttributeMaxDynamicSharedMemorySize, ATT_SMEM);

    // prep
    int n4x = ROWS * DMODEL / 4;
    split_kernel<<<(n4x + 255) / 256, 256>>>((const float4*)x, xhi, xlo, n4x);
    dim3 tgrid(DMODEL / 32, DMODEL / 32, 4);
    transpose_cvt4<<<tgrid, 256>>>(Wq, Wk, Wv, Wo, wq, wk, wv, wo);

    // fused QKV projection + rotary + split
    dim3 qkv_grid(3 * DMODEL / TN, ROWS / TM);   // (48, 32)
    gemm_qkv<<<qkv_grid, 256, GEMM_SMEM>>>(xhi, xlo, wq, wk, wv,
                                           bq, bk, bv, qhh, qll, khh, vhh);

    // tensor-core flash attention
    dim3 attn_grid(NSEQ / 64, BATCH * HEADS);   // (32, 32)
    flash_attn_mma<<<attn_grid, 128, ATT_SMEM>>>(qhh, qll, khh, vhh, ahi, alo);

    // output projection
    dim3 ggrid(DMODEL / TN, ROWS / TM);   // (16, 32)
    gemm_2p<<<ggrid, 256, GEMM_SMEM>>>(ahi, alo, wo, bo, out);
}

// round 9
// speedup vs baseline: 1.5977x; 1.0115x over previous
#include <cuda_runtime.h>
#include <cuda_fp16.h>
#include <math.h>
#include <stdint.h>

#define BATCH 2
#define NSEQ  2048
#define DMODEL 2048
#define HEADS 16
#define DHEAD 128
#define ROWS (BATCH*NSEQ)   // 4096

// ---------------------------------------------------------------------------
// scratch (device globals: no allocation allowed)
// ---------------------------------------------------------------------------
__device__ __half g_xhi[ROWS*DMODEL];
__device__ __half g_xlo[ROWS*DMODEL];
__device__ __half g_ahi[ROWS*DMODEL];
__device__ __half g_alo[ROWS*DMODEL];
__device__ __half g_qh[ROWS*DMODEL];
__device__ __half g_ql[ROWS*DMODEL];
__device__ __half g_kh[ROWS*DMODEL];
__device__ __half g_vh[ROWS*DMODEL];
__device__ __half g_wq[DMODEL*DMODEL];
__device__ __half g_wk[DMODEL*DMODEL];
__device__ __half g_wv[DMODEL*DMODEL];
__device__ __half g_wo[DMODEL*DMODEL];

// ---------------------------------------------------------------------------
// helpers
// ---------------------------------------------------------------------------
__device__ __forceinline__ uint32_t smem_u32(const void* p) {
    uint32_t a;
    asm("{ .reg .u64 t; cvta.to.shared.u64 t, %1; cvt.u32.u64 %0, t; }" : "=r"(a) : "l"(p));
    return a;
}

__device__ __forceinline__ void cp16(uint32_t dst, const void* src) {
    asm volatile("cp.async.cg.shared.global [%0], [%1], 16;" :: "r"(dst), "l"(src));
}
#define CP_COMMIT() asm volatile("cp.async.commit_group;" ::: "memory")
#define CP_WAIT(n)  asm volatile("cp.async.wait_group %0;" :: "n"(n) : "memory")

__device__ __forceinline__ void ldmx4(uint32_t addr, uint32_t& r0, uint32_t& r1,
                                      uint32_t& r2, uint32_t& r3) {
    asm volatile("ldmatrix.sync.aligned.m8n8.x4.shared.b16 {%0,%1,%2,%3}, [%4];"
                 : "=r"(r0), "=r"(r1), "=r"(r2), "=r"(r3) : "r"(addr));
}
__device__ __forceinline__ void ldmx4t(uint32_t addr, uint32_t& r0, uint32_t& r1,
                                       uint32_t& r2, uint32_t& r3) {
    asm volatile("ldmatrix.sync.aligned.m8n8.x4.trans.shared.b16 {%0,%1,%2,%3}, [%4];"
                 : "=r"(r0), "=r"(r1), "=r"(r2), "=r"(r3) : "r"(addr));
}

// fp16 inputs, fp32 accumulate
__device__ __forceinline__ void mma16816(float& c0, float& c1, float& c2, float& c3,
                                         uint32_t a0, uint32_t a1, uint32_t a2, uint32_t a3,
                                         uint32_t b0, uint32_t b1) {
    asm volatile(
        "mma.sync.aligned.m16n8k16.row.col.f32.f16.f16.f32 "
        "{%0,%1,%2,%3}, {%4,%5,%6,%7}, {%8,%9}, {%0,%1,%2,%3};"
        : "+f"(c0), "+f"(c1), "+f"(c2), "+f"(c3)
        : "r"(a0), "r"(a1), "r"(a2), "r"(a3), "r"(b0), "r"(b1));
}

__device__ __forceinline__ uint32_t packh(float a, float b) {
    __half2 t = __floats2half2_rn(a, b);
    return *(uint32_t*)&t;
}

// ---------------------------------------------------------------------------
// split: fp32 -> (hi, lo) fp16 pair
// ---------------------------------------------------------------------------
__global__ __launch_bounds__(256)
void split_kernel(const float4* __restrict__ in, __half* __restrict__ hi,
                  __half* __restrict__ lo, int n4)
{
    int i = blockIdx.x * 256 + threadIdx.x;
    if (i >= n4) return;
    float4 v = in[i];
    __half h0 = __float2half(v.x);
    __half h1 = __float2half(v.y);
    __half h2 = __float2half(v.z);
    __half h3 = __float2half(v.w);
    __half2* hp = (__half2*)(hi + 4 * (size_t)i);
    hp[0] = __half2(h0, h1);
    hp[1] = __half2(h2, h3);
    __half2* lp = (__half2*)(lo + 4 * (size_t)i);
    lp[0] = __half2(__float2half(v.x - __half2float(h0)),
                    __float2half(v.y - __half2float(h1)));
    lp[1] = __half2(__float2half(v.z - __half2float(h2)),
                    __float2half(v.w - __half2float(h3)));
}

// ---------------------------------------------------------------------------
// transpose + convert: W[K][N] fp32 -> Wt[N][K] fp16 (hi only), 4 weights
// ---------------------------------------------------------------------------
__global__ __launch_bounds__(256)
void transpose_cvt4(const float* __restrict__ W0, const float* __restrict__ W1,
                    const float* __restrict__ W2, const float* __restrict__ W3,
                    __half* __restrict__ t0, __half* __restrict__ t1,
                    __half* __restrict__ t2, __half* __restrict__ t3)
{
    int z = blockIdx.z;
    const float* W = (z == 0) ? W0 : (z == 1) ? W1 : (z == 2) ? W2 : W3;
    __half* th = (z == 0) ? t0 : (z == 1) ? t1 : (z == 2) ? t2 : t3;

    __shared__ float t[32][33];
    int n0 = blockIdx.x * 32, k0 = blockIdx.y * 32;
    int tx = threadIdx.x & 31, ty = threadIdx.x >> 5;
#pragma unroll
    for (int i = 0; i < 32; i += 8)
        t[ty + i][tx] = W[(size_t)(k0 + ty + i) * DMODEL + n0 + tx];
    __syncthreads();
#pragma unroll
    for (int i = 0; i < 32; i += 8)
        th[(size_t)(n0 + ty + i) * DMODEL + k0 + tx] = __float2half(t[tx][ty + i]);
}

// ---------------------------------------------------------------------------
// GEMM config: 2-pass fp16 split, C = (Ah+Al) @ Bh^T + bias
// CTA 128x128, KC=64, double-buffered, 3 tiles/stage (Ah, Al, Bh)
// ---------------------------------------------------------------------------
#define GK DMODEL
#define TM 128
#define TN 128
#define KC 64
#define RSTRB 144u                    // bytes per smem row (128 data + 16 pad)
#define TILE_B (128u * RSTRB)         // 18432
#define STAGE_B (3u * TILE_B)         // 55296
#define GEMM_SMEM (2u * STAGE_B)      // 110592

#define GEMM_MAINLOOP(ACC)                                                              \
    const int NCH = GK / KC;                                                            \
    copy_chunk(0, 0);                                                                   \
    const uint32_t lrow = (uint32_t)(lane & 15);                                        \
    const uint32_t lcol2 = (uint32_t)((lane >> 4) & 1) * 16u;                           \
    for (int c = 0; c < NCH; c++) {                                                     \
        int stg = c & 1;                                                                \
        if (c + 1 < NCH) {                                                              \
            copy_chunk(c + 1, stg ^ 1);                                                 \
            CP_WAIT(1);                                                                 \
        } else {                                                                        \
            CP_WAIT(0);                                                                 \
        }                                                                               \
        __syncthreads();                                                                \
        uint32_t base = sb + (uint32_t)stg * STAGE_B;                                   \
        uint32_t ah_b = base;                                                           \
        uint32_t al_b = base + TILE_B;                                                  \
        uint32_t bh_b = base + 2u * TILE_B;                                             \
        _Pragma("unroll")                                                               \
        for (int kk = 0; kk < 4; kk++) {                                                \
            uint32_t koff = (uint32_t)kk * 32u + lcol2;                                 \
            uint32_t Ah[4][4], Al[4][4];                                                \
            _Pragma("unroll")                                                           \
            for (int mi = 0; mi < 4; mi++) {                                            \
                uint32_t roff = ((uint32_t)(wm * 64 + mi * 16) + lrow) * RSTRB + koff;  \
                ldmx4(ah_b + roff, Ah[mi][0], Ah[mi][1], Ah[mi][2], Ah[mi][3]);         \
                ldmx4(al_b + roff, Al[mi][0], Al[mi][1], Al[mi][2], Al[mi][3]);         \
            }                                                                           \
            uint32_t Bh[4][2];                                                          \
            _Pragma("unroll")                                                           \
            for (int np = 0; np < 2; np++) {                                            \
                uint32_t roff = ((uint32_t)(wn * 32 + np * 16) + lrow) * RSTRB + koff;  \
                uint32_t r0, r1, r2, r3;                                                \
                ldmx4(bh_b + roff, r0, r1, r2, r3);                                     \
                Bh[np * 2][0] = r0; Bh[np * 2 + 1][0] = r1;                             \
                Bh[np * 2][1] = r2; Bh[np * 2 + 1][1] = r3;                             \
            }                                                                           \
            _Pragma("unroll")                                                           \
            for (int mi = 0; mi < 4; mi++)                                              \
                _Pragma("unroll")                                                       \
                for (int ni = 0; ni < 4; ni++) {                                        \
                    mma16816(ACC[mi][ni][0], ACC[mi][ni][1], ACC[mi][ni][2], ACC[mi][ni][3], \
                             Ah[mi][0], Ah[mi][1], Ah[mi][2], Ah[mi][3],                \
                             Bh[ni][0], Bh[ni][1]);                                     \
                    mma16816(ACC[mi][ni][0], ACC[mi][ni][1], ACC[mi][ni][2], ACC[mi][ni][3], \
                             Al[mi][0], Al[mi][1], Al[mi][2], Al[mi][3],                \
                             Bh[ni][0], Bh[ni][1]);                                     \
                }                                                                       \
        }                                                                               \
        __syncthreads();                                                                \
    }

#define GEMM_COPY_CHUNK                                                                 \
    auto copy_chunk = [&](int c, int stg) {                                             \
        int k0 = c * KC;                                                                \
        uint32_t base = sb + (uint32_t)stg * STAGE_B;                                   \
        const __half* srcs[3] = { Ahi, Alo, Bhh };                                      \
        int rows0[3] = { brow, brow, bcol };                                            \
        _Pragma("unroll")                                                               \
        for (int t = 0; t < 3; t++) {                                                   \
            const __half* src = srcs[t] + (size_t)rows0[t] * GK + k0;                   \
            uint32_t tb = base + (uint32_t)t * TILE_B;                                  \
            _Pragma("unroll")                                                           \
            for (int i = 0; i < 4; i++) {                                               \
                int s = i * 256 + tid;                                                  \
                int r = s >> 3, seg = s & 7;                                            \
                cp16(tb + (uint32_t)r * RSTRB + (uint32_t)seg * 16u,                    \
                     src + (size_t)r * GK + seg * 8);                                   \
            }                                                                           \
        }                                                                               \
        CP_COMMIT();                                                                    \
    };

// ---------------------------------------------------------------------------
// Fused QKV GEMM + rotary + fp16 split epilogue. grid (48, 32).
// q -> hi+lo; k,v -> hi only.
// ---------------------------------------------------------------------------
__global__ __launch_bounds__(256, 2)
void gemm_qkv(const __half* __restrict__ xhi, const __half* __restrict__ xlo,
              const __half* __restrict__ wq, const __half* __restrict__ wk,
              const __half* __restrict__ wv,
              const float* __restrict__ bq, const float* __restrict__ bk,
              const float* __restrict__ bv,
              __half* __restrict__ qh, __half* __restrict__ ql,
              __half* __restrict__ kh, __half* __restrict__ vh)
{
    extern __shared__ __align__(128) char smem[];
    uint32_t sb = smem_u32(smem);
    const int tid  = threadIdx.x;
    const int wid  = tid >> 5;
    const int lane = tid & 31;
    const int brow = blockIdx.y * TM;
    const int mtx  = blockIdx.x >> 4;            // 0=q, 1=k, 2=v
    const int bcol = (blockIdx.x & 15) * TN;

    const __half* Ahi = xhi;
    const __half* Alo = xlo;
    const __half* Bhh = (mtx == 0) ? wq : (mtx == 1) ? wk : wv;
    const float* bias = (mtx == 0) ? bq : (mtx == 1) ? bk : bv;

    const int wm = wid & 1;
    const int wn = wid >> 1;

    float acc[4][4][4];
#pragma unroll
    for (int i = 0; i < 4; i++)
#pragma unroll
        for (int j = 0; j < 4; j++)
#pragma unroll
            for (int r = 0; r < 4; r++) acc[i][j][r] = 0.f;

    GEMM_COPY_CHUNK
    GEMM_MAINLOOP(acc)

    // ------ fused epilogue: stage fp32 tile in smem, rotary+split, store ----
    float* ft = (float*)smem;    // [128][132] fp32 = 67584 B
    int g = lane >> 2, t4 = lane & 3;
#pragma unroll
    for (int mi = 0; mi < 4; mi++) {
        int r0 = wm * 64 + mi * 16 + g;
#pragma unroll
        for (int ni = 0; ni < 4; ni++) {
            int cl = wn * 32 + ni * 8 + 2 * t4;
            float2 b01 = *(const float2*)&bias[bcol + cl];
            *(float2*)&ft[r0 * 132 + cl] =
                make_float2(acc[mi][ni][0] + b01.x, acc[mi][ni][1] + b01.y);
            *(float2*)&ft[(r0 + 8) * 132 + cl] =
                make_float2(acc[mi][ni][2] + b01.x, acc[mi][ni][3] + b01.y);
        }
    }
    __syncthreads();

    const bool  do_rot = (mtx < 2);
    const float scale  = (mtx == 0) ? 0.08838834764831845f : 1.0f;
    int d  = tid & 63;
    int rb = tid >> 6;
    float inv_freq = __expf(-(float)d * (9.210340371976184f / 64.0f));

    for (int rr = rb; rr < 128; rr += 4) {
        int grow = brow + rr;
        float a = ft[rr * 132 + d];
        float b2 = ft[rr * 132 + d + 64];
        float oa, ob2;
        if (do_rot) {
            int n = grow & (NSEQ - 1);
            float s, c;
            sincosf((float)n * inv_freq, &s, &c);
            oa  = (a * c - b2 * s) * scale;
            ob2 = (b2 * c + a * s) * scale;
        } else {
            oa = a; ob2 = b2;
        }
        size_t base = (size_t)grow * DMODEL + bcol + d;
        if (mtx == 0) {
            __half h = __float2half(oa);
            qh[base] = h;
            ql[base] = __float2half(oa - __half2float(h));
            h = __float2half(ob2);
            qh[base + 64] = h;
            ql[base + 64] = __float2half(ob2 - __half2float(h));
        } else {
            __half* Oh = (mtx == 1) ? kh : vh;
            Oh[base]      = __float2half(oa);
            Oh[base + 64] = __float2half(ob2);
        }
    }
}

// ---------------------------------------------------------------------------
// GEMM 2-pass, fp32 output + bias — out projection
// ---------------------------------------------------------------------------
__global__ __launch_bounds__(256, 2)
void gemm_2p(const __half* __restrict__ Ahi, const __half* __restrict__ Alo,
             const __half* __restrict__ Bhh,
             const float* __restrict__ bias, float* __restrict__ C)
{
    extern __shared__ __align__(128) char smem[];
    uint32_t sb = smem_u32(smem);
    const int tid  = threadIdx.x;
    const int wid  = tid >> 5;
    const int lane = tid & 31;
    const int brow = blockIdx.y * TM;
    const int bcol = blockIdx.x * TN;

    const int wm = wid & 1;
    const int wn = wid >> 1;

    float acc[4][4][4];
#pragma unroll
    for (int i = 0; i < 4; i++)
#pragma unroll
        for (int j = 0; j < 4; j++)
#pragma unroll
            for (int r = 0; r < 4; r++) acc[i][j][r] = 0.f;

    GEMM_COPY_CHUNK
    GEMM_MAINLOOP(acc)

    int g = lane >> 2, t4 = lane & 3;
#pragma unroll
    for (int mi = 0; mi < 4; mi++) {
        int r0 = brow + wm * 64 + mi * 16 + g;
#pragma unroll
        for (int ni = 0; ni < 4; ni++) {
            int col = bcol + wn * 32 + ni * 8 + 2 * t4;
            float2 b01 = *(const float2*)&bias[col];
            float2 o0, o1;
            o0.x = acc[mi][ni][0] + b01.x;
            o0.y = acc[mi][ni][1] + b01.y;
            o1.x = acc[mi][ni][2] + b01.x;
            o1.y = acc[mi][ni][3] + b01.y;
            *(float2*)&C[(size_t)r0 * DMODEL + col]       = o0;
            *(float2*)&C[(size_t)(r0 + 8) * DMODEL + col] = o1;
        }
    }
}

// ---------------------------------------------------------------------------
// Flash attention (causal), fp16 2-pass: S=(Qh+Ql)Kh, O=(Ph+Pl)Vh.
// BR=BC=64, 128 threads, Q in regs. 4 rotating buffers (K x2, V x2):
// one commit group (K+V) per iteration, ONE wait + ONE sync per tile,
// S and PV run as a single uninterrupted mma stream.
// ---------------------------------------------------------------------------
#define ABUF_B 17408u
#define ATT_SMEM (4u * ABUF_B)        // 69632

__global__ __launch_bounds__(128)
void flash_attn_mma(const __half* __restrict__ qh, const __half* __restrict__ ql,
                    const __half* __restrict__ kh, const __half* __restrict__ vh,
                    __half* __restrict__ oh, __half* __restrict__ ol)
{
    extern __shared__ __align__(128) char smem[];
    uint32_t sb = smem_u32(smem);

    const int tid  = threadIdx.x;
    const int warp = tid >> 5;
    const int lane = tid & 31;
    const int g    = lane >> 2;
    const int q4   = lane & 3;

    const int it = gridDim.x - 1 - blockIdx.x;   // heavy tiles first
    const int bh = blockIdx.y;
    const int b = bh >> 4, h = bh & 15;
    const int i0 = it * 64;

    const size_t hoff = (size_t)b * NSEQ * DMODEL + h * DHEAD;
    const __half* qhb = qh + hoff;
    const __half* qlb = ql + hoff;
    const __half* khb = kh + hoff;
    const __half* vhb = vh + hoff;

    // copy one 64-row fp16 tile (256B rows at 272B stride), NO commit
    auto copyTile = [&](const __half* src, int row0, uint32_t buf) {
#pragma unroll
        for (int i = 0; i < 8; i++) {
            int s = i * 128 + tid;
            int r = s >> 4, seg = s & 15;
            cp16(buf + (uint32_t)r * 272u + (uint32_t)seg * 16u,
                 src + (size_t)(row0 + r) * DMODEL + seg * 8);
        }
    };

    uint32_t K0 = sb, K1 = sb + ABUF_B, V0 = sb + 2u * ABUF_B, V1 = sb + 3u * ABUF_B;

    // group 1: Q hi/lo staged in odd buffers; group 2: K(0)+V(0)
    copyTile(qhb, i0, K1);
    copyTile(qlb, i0, V1);
    CP_COMMIT();
    copyTile(khb, 0, K0);
    copyTile(vhb, 0, V0);
    CP_COMMIT();

    CP_WAIT(1);              // Q done (KV(0) may be in flight)
    __syncthreads();

    // hoist Q fragments into registers
    const uint32_t lrow = (uint32_t)(lane & 15);
    const uint32_t lseg16 = (uint32_t)(lane >> 4) * 16u;
    uint32_t Qh4[8][4], Ql4[8][4];
#pragma unroll
    for (int kk = 0; kk < 8; kk++) {
        uint32_t qoff = ((uint32_t)(warp * 16) + lrow) * 272u + lseg16 + (uint32_t)kk * 32u;
        ldmx4(K1 + qoff, Qh4[kk][0], Qh4[kk][1], Qh4[kk][2], Qh4[kk][3]);
        ldmx4(V1 + qoff, Ql4[kk][0], Ql4[kk][1], Ql4[kk][2], Ql4[kk][3]);
    }

    float m0 = -1e30f, m1 = -1e30f, l0 = 0.f, l1 = 0.f;
    float oa[16][4];
#pragma unroll
    for (int d = 0; d < 16; d++)
#pragma unroll
        for (int r = 0; r < 4; r++) oa[d][r] = 0.f;

    const int NJT = it + 1;

    for (int jt = 0; jt < NJT; jt++) {
        int stg = jt & 1;
        uint32_t kb = stg ? K1 : K0;
        uint32_t vb = stg ? V1 : V0;

        CP_WAIT(0);           // KV(jt) complete (only group in flight)
        __syncthreads();      // all warps done with jt-1 buffers / Q extraction
        if (jt + 1 < NJT) {   // prefetch KV(jt+1) into the other buffer pair
            copyTile(khb, (jt + 1) * 64, stg ? K0 : K1);
            copyTile(vhb, (jt + 1) * 64, stg ? V0 : V1);
            CP_COMMIT();
        }

        // ===== S = (Qh+Ql) @ Kh^T =====
        float s[8][4];
#pragma unroll
        for (int nb = 0; nb < 8; nb++)
#pragma unroll
            for (int r = 0; r < 4; r++) s[nb][r] = 0.f;

#pragma unroll
        for (int kk = 0; kk < 8; kk++) {
#pragma unroll
            for (int np = 0; np < 4; np++) {
                uint32_t koff = ((uint32_t)(np * 16) + lrow) * 272u + lseg16 + (uint32_t)kk * 32u;
                uint32_t h0, h1, h2, h3;
                ldmx4(kb + koff, h0, h1, h2, h3);
                int nb = np * 2;
                mma16816(s[nb][0], s[nb][1], s[nb][2], s[nb][3],
                         Qh4[kk][0], Qh4[kk][1], Qh4[kk][2], Qh4[kk][3], h0, h2);
                mma16816(s[nb][0], s[nb][1], s[nb][2], s[nb][3],
                         Ql4[kk][0], Ql4[kk][1], Ql4[kk][2], Ql4[kk][3], h0, h2);
                mma16816(s[nb + 1][0], s[nb + 1][1], s[nb + 1][2], s[nb + 1][3],
                         Qh4[kk][0], Qh4[kk][1], Qh4[kk][2], Qh4[kk][3], h1, h3);
                mma16816(s[nb + 1][0], s[nb + 1][1], s[nb + 1][2], s[nb + 1][3],
                         Ql4[kk][0], Ql4[kk][1], Ql4[kk][2], Ql4[kk][3], h1, h3);
            }
        }

        // causal mask on diagonal tile
        if (jt == it) {
            int r0 = warp * 16 + g;
            int r1 = r0 + 8;
#pragma unroll
            for (int nb = 0; nb < 8; nb++) {
                int c0 = nb * 8 + 2 * q4;
                if (c0 > r0)     s[nb][0] = -1e30f;
                if (c0 + 1 > r0) s[nb][1] = -1e30f;
                if (c0 > r1)     s[nb][2] = -1e30f;
                if (c0 + 1 > r1) s[nb][3] = -1e30f;
            }
        }

        // online softmax
        float mx0 = -1e30f, mx1 = -1e30f;
#pragma unroll
        for (int nb = 0; nb < 8; nb++) {
            mx0 = fmaxf(mx0, fmaxf(s[nb][0], s[nb][1]));
            mx1 = fmaxf(mx1, fmaxf(s[nb][2], s[nb][3]));
        }
        mx0 = fmaxf(mx0, __shfl_xor_sync(0xffffffffu, mx0, 1));
        mx0 = fmaxf(mx0, __shfl_xor_sync(0xffffffffu, mx0, 2));
        mx1 = fmaxf(mx1, __shfl_xor_sync(0xffffffffu, mx1, 1));
        mx1 = fmaxf(mx1, __shfl_xor_sync(0xffffffffu, mx1, 2));

        float m0n = fmaxf(m0, mx0), m1n = fmaxf(m1, mx1);
        float f0 = __expf(m0 - m0n), f1 = __expf(m1 - m1n);

        float sum0 = 0.f, sum1 = 0.f;
#pragma unroll
        for (int nb = 0; nb < 8; nb++) {
            s[nb][0] = __expf(s[nb][0] - m0n);
            s[nb][1] = __expf(s[nb][1] - m0n);
            s[nb][2] = __expf(s[nb][2] - m1n);
            s[nb][3] = __expf(s[nb][3] - m1n);
            sum0 += s[nb][0] + s[nb][1];
            sum1 += s[nb][2] + s[nb][3];
        }
        sum0 += __shfl_xor_sync(0xffffffffu, sum0, 1);
        sum0 += __shfl_xor_sync(0xffffffffu, sum0, 2);
        sum1 += __shfl_xor_sync(0xffffffffu, sum1, 1);
        sum1 += __shfl_xor_sync(0xffffffffu, sum1, 2);

        m0 = m0n; m1 = m1n;
        l0 = l0 * f0 + sum0;
        l1 = l1 * f1 + sum1;

#pragma unroll
        for (int d = 0; d < 16; d++) {
            oa[d][0] *= f0; oa[d][1] *= f0;
            oa[d][2] *= f1; oa[d][3] *= f1;
        }

        // P -> fp16 hi/lo A-frags
        uint32_t Ph[4][4], Pl[4][4];
#pragma unroll
        for (int kk2 = 0; kk2 < 4; kk2++) {
            int nb = 2 * kk2;
#pragma unroll
            for (int half = 0; half < 2; half++) {
                int src = nb + half;
                float p0 = s[src][0], p1 = s[src][1], p2 = s[src][2], p3 = s[src][3];
                __half2 hA = __floats2half2_rn(p0, p1);
                __half2 hB = __floats2half2_rn(p2, p3);
                Ph[kk2][half * 2 + 0] = *(uint32_t*)&hA;
                Ph[kk2][half * 2 + 1] = *(uint32_t*)&hB;
                Pl[kk2][half * 2 + 0] = packh(p0 - __half2float(__low2half(hA)),
                                              p1 - __half2float(__high2half(hA)));
                Pl[kk2][half * 2 + 1] = packh(p2 - __half2float(__low2half(hB)),
                                              p3 - __half2float(__high2half(hB)));
            }
        }

        // ===== O += (Ph+Pl) @ Vh (V already resident — no extra wait) =====
#pragma unroll
        for (int kk2 = 0; kk2 < 4; kk2++) {
#pragma unroll
            for (int dp = 0; dp < 8; dp++) {
                uint32_t voff = ((uint32_t)(kk2 * 16) + lrow) * 272u
                              + (uint32_t)dp * 32u + lseg16;
                uint32_t h0, h1, h2, h3;
                ldmx4t(vb + voff, h0, h1, h2, h3);
                int dnb = dp * 2;
                mma16816(oa[dnb][0], oa[dnb][1], oa[dnb][2], oa[dnb][3],
                         Ph[kk2][0], Ph[kk2][1], Ph[kk2][2], Ph[kk2][3], h0, h1);
                mma16816(oa[dnb][0], oa[dnb][1], oa[dnb][2], oa[dnb][3],
                         Pl[kk2][0], Pl[kk2][1], Pl[kk2][2], Pl[kk2][3], h0, h1);
                mma16816(oa[dnb + 1][0], oa[dnb + 1][1], oa[dnb + 1][2], oa[dnb + 1][3],
                         Ph[kk2][0], Ph[kk2][1], Ph[kk2][2], Ph[kk2][3], h2, h3);
                mma16816(oa[dnb + 1][0], oa[dnb + 1][1], oa[dnb + 1][2], oa[dnb + 1][3],
                         Pl[kk2][0], Pl[kk2][1], Pl[kk2][2], Pl[kk2][3], h2, h3);
            }
        }
    }

    // epilogue: normalize, split to fp16 hi/lo
    float inv0 = 1.0f / l0, inv1 = 1.0f / l1;
    int r0 = i0 + warp * 16 + g;
    __half* ohb = oh + hoff;
    __half* olb = ol + hoff;
#pragma unroll
    for (int dnb = 0; dnb < 16; dnb++) {
        int col = dnb * 8 + 2 * q4;
        float a0 = oa[dnb][0] * inv0, a1 = oa[dnb][1] * inv0;
        float b0f = oa[dnb][2] * inv1, b1f = oa[dnb][3] * inv1;
        __half2 h0 = __floats2half2_rn(a0, a1);
        __half2 h1 = __floats2half2_rn(b0f, b1f);
        *(__half2*)&ohb[(size_t)r0 * DMODEL + col] = h0;
        *(__half2*)&ohb[(size_t)(r0 + 8) * DMODEL + col] = h1;
        __half2 lo0 = __floats2half2_rn(a0 - __half2float(__low2half(h0)),
                                        a1 - __half2float(__high2half(h0)));
        __half2 lo1 = __floats2half2_rn(b0f - __half2float(__low2half(h1)),
                                        b1f - __half2float(__high2half(h1)));
        *(__half2*)&olb[(size_t)r0 * DMODEL + col] = lo0;
        *(__half2*)&olb[(size_t)(r0 + 8) * DMODEL + col] = lo1;
    }
}

// ---------------------------------------------------------------------------
extern "C" void kernel_launch(void* const* d_in, const int* in_sizes, int n_in,
                              void* d_out, int out_size)
{
    const float* x  = (const float*)d_in[0];
    const float* Wq = (const float*)d_in[1];
    const float* bq = (const float*)d_in[2];
    const float* Wk = (const float*)d_in[3];
    const float* bk = (const float*)d_in[4];
    const float* Wv = (const float*)d_in[5];
    const float* bv = (const float*)d_in[6];
    const float* Wo = (const float*)d_in[7];
    const float* bo = (const float*)d_in[8];
    float* out = (float*)d_out;

    __half *xhi, *xlo, *ahi, *alo, *qhh, *qll, *khh, *vhh;
    __half *wq, *wk, *wv, *wo;
    cudaGetSymbolAddress((void**)&xhi, g_xhi);
    cudaGetSymbolAddress((void**)&xlo, g_xlo);
    cudaGetSymbolAddress((void**)&ahi, g_ahi);
    cudaGetSymbolAddress((void**)&alo, g_alo);
    cudaGetSymbolAddress((void**)&qhh, g_qh);
    cudaGetSymbolAddress((void**)&qll, g_ql);
    cudaGetSymbolAddress((void**)&khh, g_kh);
    cudaGetSymbolAddress((void**)&vhh, g_vh);
    cudaGetSymbolAddress((void**)&wq, g_wq);
    cudaGetSymbolAddress((void**)&wk, g_wk);
    cudaGetSymbolAddress((void**)&wv, g_wv);
    cudaGetSymbolAddress((void**)&wo, g_wo);

    cudaFuncSetAttribute(gemm_qkv, cudaFuncAttributeMaxDynamicSharedMemorySize, GEMM_SMEM);
    cudaFuncSetAttribute(gemm_2p, cudaFuncAttributeMaxDynamicSharedMemorySize, GEMM_SMEM);
    cudaFuncSetAttribute(flash_attn_mma, cudaFuncAttributeMaxDynamicSharedMemorySize, ATT_SMEM);

    // prep
    int n4x = ROWS * DMODEL / 4;
    split_kernel<<<(n4x + 255) / 256, 256>>>((const float4*)x, xhi, xlo, n4x);
    dim3 tgrid(DMODEL / 32, DMODEL / 32, 4);
    transpose_cvt4<<<tgrid, 256>>>(Wq, Wk, Wv, Wo, wq, wk, wv, wo);

    // fused QKV projection + rotary + split
    dim3 qkv_grid(3 * DMODEL / TN, ROWS / TM);   // (48, 32)
    gemm_qkv<<<qkv_grid, 256, GEMM_SMEM>>>(xhi, xlo, wq, wk, wv,
                                           bq, bk, bv, qhh, qll, khh, vhh);

    // tensor-core flash attention
    dim3 attn_grid(NSEQ / 64, BATCH * HEADS);   // (32, 32)
    flash_attn_mma<<<attn_grid, 128, ATT_SMEM>>>(qhh, qll, khh, vhh, ahi, alo);

    // output projection
    dim3 ggrid(DMODEL / TN, ROWS / TM);   // (16, 32)
    gemm_2p<<<ggrid, 256, GEMM_SMEM>>>(ahi, alo, wo, bo, out);
}